// round 1
// baseline (speedup 1.0000x reference)
#include <cuda_runtime.h>
#include <cuda_bf16.h>
#include <math.h>

// ---------------------------------------------------------------------------
// Problem constants
// ---------------------------------------------------------------------------
#define BATCH 32
#define CIN   3
#define HIMG  128
#define WIMG  128
#define HID   64
#define NP    64
#define PSZ   16
#define EMB   768
#define NHEAD 4
#define DH    192          // EMB / NHEAD
#define ROWS  2048         // BATCH * 64  (token rows for every GEMM)
#define HW1   16384        // 128*128
#define HW2   4096         // 64*64
#define HC2   2048         // HC/2

// ---------------------------------------------------------------------------
// Scratch (device globals; no runtime allocation allowed)
// ---------------------------------------------------------------------------
__device__ float g_f1  [ROWS * HW1];      // conv1 out (32,64,128,128)
__device__ float g_y1  [ROWS * HW1];      // attn1 proj out
__device__ float g_pool[ROWS * HW2];      // maxpool out (32,64,64,64)
__device__ float g_f2  [ROWS * HW2];      // conv2 out
__device__ float g_y2  [ROWS * HW2];      // attn2 proj out == feats
__device__ float g_t   [ROWS * EMB];      // token embedding
__device__ float g_qkv [ROWS * 3 * EMB];
__device__ float g_att [ROWS * EMB];      // attention output (pre out-proj)
__device__ float g_o   [ROWS * EMB];      // out-proj result
__device__ float g_h1  [ROWS * HC2];      // fc1 out
__device__ float g_tp  [ROWS * 4];        // fc2 out
__device__ float g_par [ROWS * 6];        // ta,tb,tc,td,tx,ty per patch

// ---------------------------------------------------------------------------
// SGEMM: C[M,N] = A[M,K] @ B[N,K]^T + bias, optional relu.
// BM=128 fixed, BN in {128,64}, 256 threads, TM=8, TN=BN/16.
// Requires M%128==0, N%BN==0, K%16==0 (true for every call here).
// ---------------------------------------------------------------------------
template<int BN, int TN>
__global__ void __launch_bounds__(256)
sgemm_kernel(const float* __restrict__ A, const float* __restrict__ B,
             const float* __restrict__ bias, float* __restrict__ C,
             int M, int N, int K, int doRelu)
{
    __shared__ float As[16][128];
    __shared__ float Bs[16][BN];

    const int tid = threadIdx.x;
    const int tx  = tid & 15;
    const int ty  = tid >> 4;
    const int bm  = blockIdx.y * 128;
    const int bn  = blockIdx.x * BN;

    // A tile load mapping: 128 rows x 16 k, 8 floats / thread
    const int alr = tid >> 1;
    const int alk = (tid & 1) * 8;
    const float* Ap = A + (long)(bm + alr) * K + alk;

    // B tile load mapping
    int blr, blk;
    if (BN == 128) { blr = tid >> 1; blk = (tid & 1) * 8; }
    else           { blr = tid >> 2; blk = (tid & 3) * 4; }
    const float* Bp = B + (long)(bn + blr) * K + blk;

    float acc[8][TN];
    #pragma unroll
    for (int i = 0; i < 8; i++)
        #pragma unroll
        for (int j = 0; j < TN; j++) acc[i][j] = 0.f;

    for (int k0 = 0; k0 < K; k0 += 16) {
        float4 a0 = *(const float4*)(Ap);
        float4 a1 = *(const float4*)(Ap + 4);
        As[alk+0][alr] = a0.x; As[alk+1][alr] = a0.y;
        As[alk+2][alr] = a0.z; As[alk+3][alr] = a0.w;
        As[alk+4][alr] = a1.x; As[alk+5][alr] = a1.y;
        As[alk+6][alr] = a1.z; As[alk+7][alr] = a1.w;
        if (BN == 128) {
            float4 b0 = *(const float4*)(Bp);
            float4 b1 = *(const float4*)(Bp + 4);
            Bs[blk+0][blr] = b0.x; Bs[blk+1][blr] = b0.y;
            Bs[blk+2][blr] = b0.z; Bs[blk+3][blr] = b0.w;
            Bs[blk+4][blr] = b1.x; Bs[blk+5][blr] = b1.y;
            Bs[blk+6][blr] = b1.z; Bs[blk+7][blr] = b1.w;
        } else {
            float4 b0 = *(const float4*)(Bp);
            Bs[blk+0][blr] = b0.x; Bs[blk+1][blr] = b0.y;
            Bs[blk+2][blr] = b0.z; Bs[blk+3][blr] = b0.w;
        }
        Ap += 16; Bp += 16;
        __syncthreads();

        #pragma unroll
        for (int kk = 0; kk < 16; kk++) {
            float a[8], bf[TN];
            *(float4*)&a[0] = *(const float4*)&As[kk][ty*8];
            *(float4*)&a[4] = *(const float4*)&As[kk][ty*8 + 4];
            if (TN == 8) {
                *(float4*)&bf[0] = *(const float4*)&Bs[kk][tx*8];
                *(float4*)&bf[4] = *(const float4*)&Bs[kk][tx*8 + 4];
            } else {
                *(float4*)&bf[0] = *(const float4*)&Bs[kk][tx*4];
            }
            #pragma unroll
            for (int i = 0; i < 8; i++)
                #pragma unroll
                for (int j = 0; j < TN; j++)
                    acc[i][j] = fmaf(a[i], bf[j], acc[i][j]);
        }
        __syncthreads();
    }

    float bv[TN];
    #pragma unroll
    for (int j = 0; j < TN; j++) bv[j] = bias[bn + tx*TN + j];

    #pragma unroll
    for (int i = 0; i < 8; i++) {
        long m = bm + ty*8 + i;
        float* Cp = C + m * (long)N + bn + tx*TN;
        #pragma unroll
        for (int j = 0; j < TN; j += 4) {
            float4 v;
            v.x = acc[i][j+0] + bv[j+0];
            v.y = acc[i][j+1] + bv[j+1];
            v.z = acc[i][j+2] + bv[j+2];
            v.w = acc[i][j+3] + bv[j+3];
            if (doRelu) {
                v.x = fmaxf(v.x, 0.f); v.y = fmaxf(v.y, 0.f);
                v.z = fmaxf(v.z, 0.f); v.w = fmaxf(v.w, 0.f);
            }
            *(float4*)(Cp + j) = v;
        }
    }
}

// ---------------------------------------------------------------------------
// 3x3 SAME conv + relu. Tile: 16(x) x 32(y) pixels, 16 out-channels per block,
// each thread computes 2 pixels x 16 oc. IC chunked by ICC.
// grid: x = (W/16)*(H/32), y = BATCH*4 (4 oc groups of 16).  OC = 64 fixed.
// ---------------------------------------------------------------------------
template<int IC, int ICC, int HH, int WW>
__global__ void __launch_bounds__(256)
conv3x3_relu_kernel(const float* __restrict__ in, const float* __restrict__ w,
                    const float* __restrict__ bias, float* __restrict__ out)
{
    __shared__ float sIn[ICC][34][18];
    __shared__ float sW[16][ICC][9];

    const int tx = threadIdx.x & 15;
    const int ty = threadIdx.x >> 4;
    const int tilesX = WW / 16;
    const int bx = (blockIdx.x % tilesX) * 16;
    const int by = (blockIdx.x / tilesX) * 32;
    const int b   = blockIdx.y >> 2;
    const int ocg = (blockIdx.y & 3) * 16;

    float acc0[16], acc1[16];
    #pragma unroll
    for (int oc = 0; oc < 16; oc++) { acc0[oc] = 0.f; acc1[oc] = 0.f; }

    for (int icc = 0; icc < IC; icc += ICC) {
        for (int i = threadIdx.x; i < ICC*34*18; i += 256) {
            int col = i % 18; int t = i / 18; int row = t % 34; int ic = t / 34;
            int gx = bx + col - 1, gy = by + row - 1;
            float v = 0.f;
            if (gx >= 0 && gx < WW && gy >= 0 && gy < HH)
                v = in[(((long)b*IC + icc + ic)*HH + gy)*WW + gx];
            sIn[ic][row][col] = v;
        }
        for (int i = threadIdx.x; i < 16*ICC*9; i += 256) {
            int kk = i % 9; int t = i / 9; int ic = t % ICC; int oc = t / ICC;
            sW[oc][ic][kk] = w[((ocg + oc)*IC + icc + ic)*9 + kk];
        }
        __syncthreads();

        #pragma unroll
        for (int ic = 0; ic < ICC; ic++) {
            #pragma unroll
            for (int ky = 0; ky < 3; ky++) {
                #pragma unroll
                for (int kx = 0; kx < 3; kx++) {
                    float iv0 = sIn[ic][ty + ky][tx + kx];
                    float iv1 = sIn[ic][ty + 16 + ky][tx + kx];
                    #pragma unroll
                    for (int oc = 0; oc < 16; oc++) {
                        float wv = sW[oc][ic][ky*3 + kx];
                        acc0[oc] = fmaf(iv0, wv, acc0[oc]);
                        acc1[oc] = fmaf(iv1, wv, acc1[oc]);
                    }
                }
            }
        }
        __syncthreads();
    }

    #pragma unroll
    for (int oc = 0; oc < 16; oc++) {
        float bv = bias[ocg + oc];
        long o0 = (((long)b*64 + ocg + oc)*HH + by + ty)*WW + bx + tx;
        out[o0]          = fmaxf(acc0[oc] + bv, 0.f);
        out[o0 + 16*WW]  = fmaxf(acc1[oc] + bv, 0.f);
    }
}

// ---------------------------------------------------------------------------
// MHA core: one block per (b, head). 64 tokens, dh = 192.
// qkv rows: (b*64 + t) * 2304, layout [q|k|v] each 768, head h at h*192.
// Dynamic smem: Q,K,V padded stride 193; scores padded stride 65.
// ---------------------------------------------------------------------------
#define QKV_STRIDE 193
#define SC_STRIDE  65
#define ATTN_SMEM  ((3*64*QKV_STRIDE + 64*SC_STRIDE) * (int)sizeof(float))

__global__ void attn_kernel(const float* __restrict__ qkv, float* __restrict__ out)
{
    extern __shared__ float sm[];
    float* sQ = sm;
    float* sK = sQ + 64*QKV_STRIDE;
    float* sV = sK + 64*QKV_STRIDE;
    float* sS = sV + 64*QKV_STRIDE;

    const int bh = blockIdx.x;        // b*4 + h
    const int b  = bh >> 2;
    const int h  = bh & 3;
    const int base = b * 64;
    const float scale = 0.07216878364870323f; // 1/sqrt(192)

    for (int i = threadIdx.x; i < 64*DH; i += 256) {
        int r = i / DH, c = i % DH;
        long off = (long)(base + r)*2304 + h*DH + c;
        sQ[r*QKV_STRIDE + c] = qkv[off];
        sK[r*QKV_STRIDE + c] = qkv[off + 768];
        sV[r*QKV_STRIDE + c] = qkv[off + 1536];
    }
    __syncthreads();

    for (int e = threadIdx.x; e < 64*64; e += 256) {
        int i = e >> 6, j = e & 63;
        const float* q = sQ + i*QKV_STRIDE;
        const float* k = sK + j*QKV_STRIDE;
        float s = 0.f;
        #pragma unroll 8
        for (int d = 0; d < DH; d++) s = fmaf(q[d], k[d], s);
        sS[i*SC_STRIDE + j] = s * scale;
    }
    __syncthreads();

    if (threadIdx.x < 64) {
        float* row = sS + threadIdx.x * SC_STRIDE;
        float mx = row[0];
        #pragma unroll 8
        for (int j = 1; j < 64; j++) mx = fmaxf(mx, row[j]);
        float sum = 0.f;
        #pragma unroll 8
        for (int j = 0; j < 64; j++) { float e = __expf(row[j] - mx); row[j] = e; sum += e; }
        float inv = 1.f / sum;
        #pragma unroll 8
        for (int j = 0; j < 64; j++) row[j] *= inv;
    }
    __syncthreads();

    for (int e = threadIdx.x; e < 64*DH; e += 256) {
        int i = e / DH, d = e % DH;
        const float* p = sS + i*SC_STRIDE;
        float s = 0.f;
        #pragma unroll 8
        for (int j = 0; j < 64; j++) s = fmaf(p[j], sV[j*QKV_STRIDE + d], s);
        out[(long)(base + i)*EMB + h*DH + d] = s;
    }
}

// ---------------------------------------------------------------------------
// 2x2 maxpool (32,64,128,128) -> (32,64,64,64)
// ---------------------------------------------------------------------------
__global__ void maxpool_kernel(const float* __restrict__ in, float* __restrict__ out)
{
    int idx = blockIdx.x * blockDim.x + threadIdx.x;
    if (idx >= ROWS * HW2) return;
    int ox = idx & 63;
    int oy = (idx >> 6) & 63;
    int cb = idx >> 12;
    const float* p = in + ((long)cb*128 + oy*2)*128 + ox*2;
    out[idx] = fmaxf(fmaxf(p[0], p[1]), fmaxf(p[128], p[129]));
}

// ---------------------------------------------------------------------------
// fc2: (2048,2048) @ (4,2048)^T + bias -> (2048,4). One warp per row.
// ---------------------------------------------------------------------------
__global__ void fc2_kernel(const float* __restrict__ h1, const float* __restrict__ w,
                           const float* __restrict__ bias, float* __restrict__ tp)
{
    int warp = (blockIdx.x * blockDim.x + threadIdx.x) >> 5;
    int lane = threadIdx.x & 31;
    if (warp >= ROWS) return;
    const float* row = h1 + (long)warp * HC2;
    float a0 = 0.f, a1 = 0.f, a2 = 0.f, a3 = 0.f;
    for (int k = lane; k < HC2; k += 32) {
        float hv = row[k];
        a0 = fmaf(hv, w[k],          a0);
        a1 = fmaf(hv, w[HC2   + k],  a1);
        a2 = fmaf(hv, w[2*HC2 + k],  a2);
        a3 = fmaf(hv, w[3*HC2 + k],  a3);
    }
    #pragma unroll
    for (int o = 16; o > 0; o >>= 1) {
        a0 += __shfl_xor_sync(0xffffffffu, a0, o);
        a1 += __shfl_xor_sync(0xffffffffu, a1, o);
        a2 += __shfl_xor_sync(0xffffffffu, a2, o);
        a3 += __shfl_xor_sync(0xffffffffu, a3, o);
    }
    if (lane == 0) {
        tp[warp*4 + 0] = a0 + bias[0];
        tp[warp*4 + 1] = a1 + bias[1];
        tp[warp*4 + 2] = a2 + bias[2];
        tp[warp*4 + 3] = a3 + bias[3];
    }
}

// ---------------------------------------------------------------------------
// Affine parameter computation + translate output.
// ---------------------------------------------------------------------------
__global__ void params_kernel(const float* __restrict__ tp, float* __restrict__ par,
                              float* __restrict__ out_translate)
{
    int i = blockIdx.x * blockDim.x + threadIdx.x;
    if (i >= ROWS) return;
    float t0 = tp[i*4+0], t1 = tp[i*4+1], t2 = tp[i*4+2], t3 = tp[i*4+3];
    float trx = tanhf(t0);
    float trY = tanhf(t1);
    float s   = 0.3f / (1.f + expf(-t2));
    float rot = tanhf(t3) * 3.14159265358979323846f;
    float sn, cs;
    sincosf(rot, &sn, &cs);
    float x_ext = fminf(s*fabsf(cs) + s*fabsf(sn), 1.f);
    float y_ext = fminf(s*fabsf(sn) + s*fabsf(cs), 1.f);
    float txv = trx * (1.f - x_ext);
    float tyv = trY * (1.f - y_ext);
    par[i*6+0] =  s*cs;
    par[i*6+1] = -s*sn;
    par[i*6+2] =  s*sn;
    par[i*6+3] =  s*cs;
    par[i*6+4] =  txv;
    par[i*6+5] =  tyv;
    out_translate[i*2+0] = txv;
    out_translate[i*2+1] = tyv;
}

// ---------------------------------------------------------------------------
// Bilinear grid sample -> patches (B*NP, C, P, P)
// ---------------------------------------------------------------------------
__global__ void gridsample_kernel(const float* __restrict__ x,
                                  const float* __restrict__ par,
                                  float* __restrict__ out)
{
    int idx = blockIdx.x * blockDim.x + threadIdx.x;
    const int total = ROWS * CIN * PSZ * PSZ;
    if (idx >= total) return;
    int px = idx & 15;
    int py = (idx >> 4) & 15;
    int c  = (idx >> 8) % 3;
    int bp = idx / (3*256);
    int b  = bp >> 6;

    float ta = par[bp*6+0], tb = par[bp*6+1], tc = par[bp*6+2];
    float td = par[bp*6+3], txp = par[bp*6+4], typ = par[bp*6+5];

    float bxv = (2.f*px + 1.f) / 16.f - 1.f;
    float byv = (2.f*py + 1.f) / 16.f - 1.f;
    float gx = ta*bxv + tb*byv + txp;
    float gy = tc*bxv + td*byv + typ;

    float xs = ((gx + 1.f) * (float)WIMG - 1.f) * 0.5f;
    float ys = ((gy + 1.f) * (float)HIMG - 1.f) * 0.5f;
    float x0f = floorf(xs), y0f = floorf(ys);
    float wx = xs - x0f, wy = ys - y0f;
    int x0 = (int)x0f, y0 = (int)y0f;

    const float* img = x + ((long)b*3 + c) * (HIMG*WIMG);
    float v00 = 0.f, v01 = 0.f, v10 = 0.f, v11 = 0.f;
    bool xv0 = (x0   >= 0) & (x0   < WIMG);
    bool xv1 = (x0+1 >= 0) & (x0+1 < WIMG);
    bool yv0 = (y0   >= 0) & (y0   < HIMG);
    bool yv1 = (y0+1 >= 0) & (y0+1 < HIMG);
    if (yv0 & xv0) v00 = img[y0*WIMG + x0];
    if (yv0 & xv1) v01 = img[y0*WIMG + x0 + 1];
    if (yv1 & xv0) v10 = img[(y0+1)*WIMG + x0];
    if (yv1 & xv1) v11 = img[(y0+1)*WIMG + x0 + 1];

    out[idx] = v00*(1.f-wx)*(1.f-wy) + v01*wx*(1.f-wy)
             + v10*(1.f-wx)*wy       + v11*wx*wy;
}

// ---------------------------------------------------------------------------
// Host-side GEMM dispatch
// ---------------------------------------------------------------------------
static void run_gemm(const float* A, const float* B, const float* bias, float* C,
                     int M, int N, int K, int relu)
{
    if ((N / 128) * (M / 128) >= 148) {
        dim3 grid(N / 128, M / 128);
        sgemm_kernel<128, 8><<<grid, 256>>>(A, B, bias, C, M, N, K, relu);
    } else {
        dim3 grid(N / 64, M / 128);
        sgemm_kernel<64, 4><<<grid, 256>>>(A, B, bias, C, M, N, K, relu);
    }
}

// ---------------------------------------------------------------------------
// kernel_launch
// ---------------------------------------------------------------------------
extern "C" void kernel_launch(void* const* d_in, const int* in_sizes, int n_in,
                              void* d_out, int out_size)
{
    const float* x        = (const float*)d_in[0];
    const float* conv1_w  = (const float*)d_in[1];
    const float* conv1_b  = (const float*)d_in[2];
    const float* a1_in_w  = (const float*)d_in[3];
    const float* a1_in_b  = (const float*)d_in[4];
    const float* a1_qkv_w = (const float*)d_in[5];
    const float* a1_qkv_b = (const float*)d_in[6];
    const float* a1_out_w = (const float*)d_in[7];
    const float* a1_out_b = (const float*)d_in[8];
    const float* a1_proj_w= (const float*)d_in[9];
    const float* a1_proj_b= (const float*)d_in[10];
    const float* conv2_w  = (const float*)d_in[11];
    const float* conv2_b  = (const float*)d_in[12];
    const float* a2_in_w  = (const float*)d_in[13];
    const float* a2_in_b  = (const float*)d_in[14];
    const float* a2_qkv_w = (const float*)d_in[15];
    const float* a2_qkv_b = (const float*)d_in[16];
    const float* a2_out_w = (const float*)d_in[17];
    const float* a2_out_b = (const float*)d_in[18];
    const float* a2_proj_w= (const float*)d_in[19];
    const float* a2_proj_b= (const float*)d_in[20];
    const float* fc1_w    = (const float*)d_in[21];
    const float* fc1_b    = (const float*)d_in[22];
    const float* fc2_w    = (const float*)d_in[23];
    const float* fc2_b    = (const float*)d_in[24];

    float* out = (float*)d_out;
    float* out_patches   = out;                      // 2048*3*16*16
    float* out_translate = out + ROWS*CIN*PSZ*PSZ;   // 2048*2

    float *f1, *y1, *pool, *f2, *y2, *t, *qkv, *att, *o, *h1, *tp, *par;
    cudaGetSymbolAddress((void**)&f1,   g_f1);
    cudaGetSymbolAddress((void**)&y1,   g_y1);
    cudaGetSymbolAddress((void**)&pool, g_pool);
    cudaGetSymbolAddress((void**)&f2,   g_f2);
    cudaGetSymbolAddress((void**)&y2,   g_y2);
    cudaGetSymbolAddress((void**)&t,    g_t);
    cudaGetSymbolAddress((void**)&qkv,  g_qkv);
    cudaGetSymbolAddress((void**)&att,  g_att);
    cudaGetSymbolAddress((void**)&o,    g_o);
    cudaGetSymbolAddress((void**)&h1,   g_h1);
    cudaGetSymbolAddress((void**)&tp,   g_tp);
    cudaGetSymbolAddress((void**)&par,  g_par);

    cudaFuncSetAttribute(attn_kernel,
                         cudaFuncAttributeMaxDynamicSharedMemorySize, ATTN_SMEM);

    // --- stage 1: conv1 + relu  (32,3,128,128) -> (32,64,128,128)
    conv3x3_relu_kernel<3, 3, 128, 128>
        <<<dim3((128/16)*(128/32), BATCH*4), 256>>>(x, conv1_w, conv1_b, f1);

    // --- attention block 1 (tokens = 64 channels)
    run_gemm(f1, a1_in_w, a1_in_b, t, ROWS, EMB, HW1, 0);
    run_gemm(t, a1_qkv_w, a1_qkv_b, qkv, ROWS, 3*EMB, EMB, 0);
    attn_kernel<<<BATCH*NHEAD, 256, ATTN_SMEM>>>(qkv, att);
    run_gemm(att, a1_out_w, a1_out_b, o, ROWS, EMB, EMB, 0);
    run_gemm(o, a1_proj_w, a1_proj_b, y1, ROWS, HW1, EMB, 0);

    // --- maxpool
    maxpool_kernel<<<(ROWS*HW2 + 255)/256, 256>>>(y1, pool);

    // --- conv2 + relu (32,64,64,64) -> (32,64,64,64)
    conv3x3_relu_kernel<64, 8, 64, 64>
        <<<dim3((64/16)*(64/32), BATCH*4), 256>>>(pool, conv2_w, conv2_b, f2);

    // --- attention block 2
    run_gemm(f2, a2_in_w, a2_in_b, t, ROWS, EMB, HW2, 0);
    run_gemm(t, a2_qkv_w, a2_qkv_b, qkv, ROWS, 3*EMB, EMB, 0);
    attn_kernel<<<BATCH*NHEAD, 256, ATTN_SMEM>>>(qkv, att);
    run_gemm(att, a2_out_w, a2_out_b, o, ROWS, EMB, EMB, 0);
    run_gemm(o, a2_proj_w, a2_proj_b, y2, ROWS, HW2, EMB, 0);

    // --- head
    run_gemm(y2, fc1_w, fc1_b, h1, ROWS, HC2, HW2, 1);          // relu
    fc2_kernel<<<(ROWS*32 + 255)/256, 256>>>(h1, fc2_w, fc2_b, tp);
    params_kernel<<<(ROWS + 255)/256, 256>>>(tp, par, out_translate);
    gridsample_kernel<<<(ROWS*CIN*PSZ*PSZ + 255)/256, 256>>>(x, par, out_patches);
}

// round 3
// speedup vs baseline: 1.2255x; 1.2255x over previous
#include <cuda_runtime.h>
#include <cuda_bf16.h>
#include <math.h>

// ---------------------------------------------------------------------------
// Problem constants
// ---------------------------------------------------------------------------
#define BATCH 32
#define CIN   3
#define HIMG  128
#define WIMG  128
#define PSZ   16
#define EMB   768
#define DH    192
#define ROWS  2048         // BATCH * 64
#define HW1   16384
#define HW2   4096
#define HC2   2048

typedef unsigned long long u64;

// ---------------------------------------------------------------------------
// f32x2 helpers (FFMA2 path — exact fp32, 2x FMA throughput on sm_103a)
// ---------------------------------------------------------------------------
__device__ __forceinline__ u64 pk2(float lo, float hi) {
    u64 r; asm("mov.b64 %0, {%1,%2};" : "=l"(r) : "f"(lo), "f"(hi)); return r;
}
__device__ __forceinline__ void fma2(u64& d, u64 a, u64 b) {
    asm("fma.rn.f32x2 %0, %1, %2, %0;" : "+l"(d) : "l"(a), "l"(b));
}
__device__ __forceinline__ float2 upk2(u64 v) {
    float2 f; asm("mov.b64 {%0,%1}, %2;" : "=f"(f.x), "=f"(f.y) : "l"(v)); return f;
}

// ---------------------------------------------------------------------------
// Scratch (device globals; no runtime allocation allowed)
// ---------------------------------------------------------------------------
__device__ float g_f1  [ROWS * HW1];
__device__ float g_y1  [ROWS * HW1];
__device__ float g_pool[ROWS * HW2];
__device__ float g_f2  [ROWS * HW2];
__device__ float g_y2  [ROWS * HW2];
__device__ float g_t   [ROWS * EMB];
__device__ float g_qkv [ROWS * 3 * EMB];
__device__ float g_att [ROWS * EMB];
__device__ float g_o   [ROWS * EMB];
__device__ float g_h1  [ROWS * HC2];
__device__ float g_tp  [ROWS * 4];
__device__ float g_par [ROWS * 6];
__device__ float g_part[2 * ROWS * EMB];   // split-K partials (split=2, N<=768)

// ---------------------------------------------------------------------------
// SGEMM v2: C[M,N] = A[M,K] @ B[N,K]^T (+bias,+relu) with FFMA2 inner loop,
// double-buffered smem, optional 2-way split-K (partials, bias in reduce).
// BM=128, BN in {128,64}, 256 threads, TM=8, TN=BN/16.
// ---------------------------------------------------------------------------
#define STORE_TILE(S)                                                         \
    do {                                                                      \
        As[S][alk+0][alr]=ra0.x; As[S][alk+1][alr]=ra0.y;                     \
        As[S][alk+2][alr]=ra0.z; As[S][alk+3][alr]=ra0.w;                     \
        As[S][alk+4][alr]=ra1.x; As[S][alk+5][alr]=ra1.y;                     \
        As[S][alk+6][alr]=ra1.z; As[S][alk+7][alr]=ra1.w;                     \
        if (BN == 128) {                                                      \
            Bs[S][blk+0][blr]=rb0.x; Bs[S][blk+1][blr]=rb0.y;                 \
            Bs[S][blk+2][blr]=rb0.z; Bs[S][blk+3][blr]=rb0.w;                 \
            Bs[S][blk+4][blr]=rb1.x; Bs[S][blk+5][blr]=rb1.y;                 \
            Bs[S][blk+6][blr]=rb1.z; Bs[S][blk+7][blr]=rb1.w;                 \
        } else {                                                              \
            Bs[S][blk+0][blr]=rb0.x; Bs[S][blk+1][blr]=rb0.y;                 \
            Bs[S][blk+2][blr]=rb0.z; Bs[S][blk+3][blr]=rb0.w;                 \
        }                                                                     \
    } while (0)

template<int BN, int TN>
__global__ void __launch_bounds__(256)
sgemm2_kernel(const float* __restrict__ A, const float* __restrict__ B,
              const float* __restrict__ bias, float* __restrict__ C,
              int M, int N, int K, int doRelu, int kSplit,
              float* __restrict__ part)
{
    __shared__ float As[2][16][128];
    __shared__ float Bs[2][16][BN];

    const int tid = threadIdx.x;
    const int tx  = tid & 15;
    const int ty  = tid >> 4;
    const int bm  = blockIdx.y * 128;
    const int bn  = blockIdx.x * BN;

    int kLen = K, kBase = 0;
    if (kSplit > 1) { kLen = K / kSplit; kBase = blockIdx.z * kLen; }

    const int alr = tid >> 1;
    const int alk = (tid & 1) * 8;
    const float* Ap = A + (size_t)(bm + alr) * K + kBase + alk;
    int blr, blk;
    if (BN == 128) { blr = tid >> 1; blk = (tid & 1) * 8; }
    else           { blr = tid >> 2; blk = (tid & 3) * 4; }
    const float* Bp = B + (size_t)(bn + blr) * K + kBase + blk;

    float4 ra0, ra1, rb0, rb1;
    rb1 = make_float4(0.f, 0.f, 0.f, 0.f);

    // prologue: load tile 0 -> buf 0
    ra0 = *(const float4*)Ap; ra1 = *(const float4*)(Ap + 4);
    rb0 = *(const float4*)Bp;
    if (BN == 128) rb1 = *(const float4*)(Bp + 4);
    Ap += 16; Bp += 16;
    STORE_TILE(0);
    __syncthreads();

    u64 acc[8][TN/2];
    #pragma unroll
    for (int i = 0; i < 8; i++)
        #pragma unroll
        for (int j = 0; j < TN/2; j++) acc[i][j] = 0ull;

    const int nT = kLen >> 4;
    int buf = 0;
    for (int tI = 0; tI < nT; tI++) {
        const bool hasNext = (tI + 1 < nT);
        if (hasNext) {
            ra0 = *(const float4*)Ap; ra1 = *(const float4*)(Ap + 4);
            rb0 = *(const float4*)Bp;
            if (BN == 128) rb1 = *(const float4*)(Bp + 4);
            Ap += 16; Bp += 16;
        }
        #pragma unroll
        for (int kk = 0; kk < 16; kk++) {
            float4 a0 = *(const float4*)&As[buf][kk][ty*8];
            float4 a1 = *(const float4*)&As[buf][kk][ty*8 + 4];
            u64 b2[TN/2];
            const u64* bp2 = (const u64*)&Bs[buf][kk][tx*TN];
            #pragma unroll
            for (int j = 0; j < TN/2; j++) b2[j] = bp2[j];
            float av[8] = {a0.x, a0.y, a0.z, a0.w, a1.x, a1.y, a1.z, a1.w};
            #pragma unroll
            for (int i = 0; i < 8; i++) {
                u64 ap = pk2(av[i], av[i]);
                #pragma unroll
                for (int j = 0; j < TN/2; j++) fma2(acc[i][j], ap, b2[j]);
            }
        }
        if (hasNext) {
            const int nb = buf ^ 1;
            As[nb][alk+0][alr]=ra0.x; As[nb][alk+1][alr]=ra0.y;
            As[nb][alk+2][alr]=ra0.z; As[nb][alk+3][alr]=ra0.w;
            As[nb][alk+4][alr]=ra1.x; As[nb][alk+5][alr]=ra1.y;
            As[nb][alk+6][alr]=ra1.z; As[nb][alk+7][alr]=ra1.w;
            if (BN == 128) {
                Bs[nb][blk+0][blr]=rb0.x; Bs[nb][blk+1][blr]=rb0.y;
                Bs[nb][blk+2][blr]=rb0.z; Bs[nb][blk+3][blr]=rb0.w;
                Bs[nb][blk+4][blr]=rb1.x; Bs[nb][blk+5][blr]=rb1.y;
                Bs[nb][blk+6][blr]=rb1.z; Bs[nb][blk+7][blr]=rb1.w;
            } else {
                Bs[nb][blk+0][blr]=rb0.x; Bs[nb][blk+1][blr]=rb0.y;
                Bs[nb][blk+2][blr]=rb0.z; Bs[nb][blk+3][blr]=rb0.w;
            }
        }
        __syncthreads();
        buf ^= 1;
    }

    if (kSplit > 1) {
        float* Cp0 = part + (size_t)blockIdx.z * M * N;
        #pragma unroll
        for (int i = 0; i < 8; i++) {
            float* Cp = Cp0 + (size_t)(bm + ty*8 + i) * N + bn + tx*TN;
            #pragma unroll
            for (int j = 0; j < TN/2; j += 2) {
                float2 v0 = upk2(acc[i][j]);
                float2 v1 = upk2(acc[i][j+1]);
                float4 v = make_float4(v0.x, v0.y, v1.x, v1.y);
                *(float4*)(Cp + j*2) = v;
            }
        }
    } else {
        float bv[TN];
        #pragma unroll
        for (int j = 0; j < TN; j++) bv[j] = bias[bn + tx*TN + j];
        #pragma unroll
        for (int i = 0; i < 8; i++) {
            float* Cp = C + (size_t)(bm + ty*8 + i) * N + bn + tx*TN;
            #pragma unroll
            for (int j = 0; j < TN/2; j += 2) {
                float2 v0 = upk2(acc[i][j]);
                float2 v1 = upk2(acc[i][j+1]);
                float4 v;
                v.x = v0.x + bv[j*2+0]; v.y = v0.y + bv[j*2+1];
                v.z = v1.x + bv[j*2+2]; v.w = v1.y + bv[j*2+3];
                if (doRelu) {
                    v.x = fmaxf(v.x, 0.f); v.y = fmaxf(v.y, 0.f);
                    v.z = fmaxf(v.z, 0.f); v.w = fmaxf(v.w, 0.f);
                }
                *(float4*)(Cp + j*2) = v;
            }
        }
    }
}

// split-K=2 reduce: C = part0 + part1 + bias
__global__ void splitk_reduce_kernel(const float* __restrict__ part,
                                     const float* __restrict__ bias,
                                     float* __restrict__ C, int MN, int N)
{
    int idx = blockIdx.x * blockDim.x + threadIdx.x;
    if (idx >= MN) return;
    C[idx] = part[idx] + part[idx + MN] + bias[idx % N];
}

// ---------------------------------------------------------------------------
// 3x3 SAME conv + relu with FFMA2. Tile 16(x) x 64(y), 8 oc per block,
// each thread: 4 pixels x 8 oc (pixel pairs packed f32x2).
// grid.x = (WW/16)*(HH/64), grid.y = BATCH*8. OC=64 fixed.
// ---------------------------------------------------------------------------
template<int IC, int ICC, int HH, int WW>
__global__ void __launch_bounds__(256)
conv3x3_relu2_kernel(const float* __restrict__ in, const float* __restrict__ w,
                     const float* __restrict__ bias, float* __restrict__ out)
{
    __shared__ float  sIn[ICC][66][18];
    __shared__ float2 sW2[8][ICC][9];

    const int tx = threadIdx.x & 15;
    const int ty = threadIdx.x >> 4;
    const int tilesX = WW / 16;
    const int bx = (blockIdx.x % tilesX) * 16;
    const int by = (blockIdx.x / tilesX) * 64;
    const int b   = blockIdx.y >> 3;
    const int ocg = (blockIdx.y & 7) * 8;

    u64 a01[8], a23[8];
    #pragma unroll
    for (int oc = 0; oc < 8; oc++) { a01[oc] = 0ull; a23[oc] = 0ull; }

    for (int icc = 0; icc < IC; icc += ICC) {
        for (int i = threadIdx.x; i < ICC*66*18; i += 256) {
            int col = i % 18; int t = i / 18; int row = t % 66; int ic = t / 66;
            int gx = bx + col - 1, gy = by + row - 1;
            float v = 0.f;
            if (gx >= 0 && gx < WW && gy >= 0 && gy < HH)
                v = in[(((size_t)b*IC + icc + ic)*HH + gy)*WW + gx];
            sIn[ic][row][col] = v;
        }
        for (int i = threadIdx.x; i < 8*ICC*9; i += 256) {
            int kk = i % 9; int t = i / 9; int ic = t % ICC; int oc = t / ICC;
            float wv = w[((ocg + oc)*IC + icc + ic)*9 + kk];
            sW2[oc][ic][kk] = make_float2(wv, wv);
        }
        __syncthreads();

        #pragma unroll
        for (int ic = 0; ic < ICC; ic++) {
            #pragma unroll
            for (int ky = 0; ky < 3; ky++) {
                #pragma unroll
                for (int kx = 0; kx < 3; kx++) {
                    float iv0 = sIn[ic][ty      + ky][tx + kx];
                    float iv1 = sIn[ic][ty + 16 + ky][tx + kx];
                    float iv2 = sIn[ic][ty + 32 + ky][tx + kx];
                    float iv3 = sIn[ic][ty + 48 + ky][tx + kx];
                    u64 p01 = pk2(iv0, iv1);
                    u64 p23 = pk2(iv2, iv3);
                    #pragma unroll
                    for (int oc = 0; oc < 8; oc++) {
                        u64 wv = *(const u64*)&sW2[oc][ic][ky*3 + kx];
                        fma2(a01[oc], p01, wv);
                        fma2(a23[oc], p23, wv);
                    }
                }
            }
        }
        __syncthreads();
    }

    #pragma unroll
    for (int oc = 0; oc < 8; oc++) {
        float bv = bias[ocg + oc];
        float2 v01 = upk2(a01[oc]);
        float2 v23 = upk2(a23[oc]);
        size_t base = (((size_t)b*64 + ocg + oc)*HH + by + ty)*WW + bx + tx;
        out[base            ] = fmaxf(v01.x + bv, 0.f);
        out[base + 16ull*WW ] = fmaxf(v01.y + bv, 0.f);
        out[base + 32ull*WW ] = fmaxf(v23.x + bv, 0.f);
        out[base + 48ull*WW ] = fmaxf(v23.y + bv, 0.f);
    }
}

// ---------------------------------------------------------------------------
// MHA core: one block per (b, head). 64 tokens, dh=192. 512 threads.
// ---------------------------------------------------------------------------
#define QKV_STRIDE 193
#define SC_STRIDE  65
#define ATTN_SMEM  ((3*64*QKV_STRIDE + 64*SC_STRIDE) * (int)sizeof(float))

__global__ void attn_kernel(const float* __restrict__ qkv, float* __restrict__ out)
{
    extern __shared__ float sm[];
    float* sQ = sm;
    float* sK = sQ + 64*QKV_STRIDE;
    float* sV = sK + 64*QKV_STRIDE;
    float* sS = sV + 64*QKV_STRIDE;

    const int bh = blockIdx.x;
    const int b  = bh >> 2;
    const int h  = bh & 3;
    const int base = b * 64;
    const float scale = 0.07216878364870323f; // 1/sqrt(192)

    for (int i = threadIdx.x; i < 64*DH; i += 512) {
        int r = i / DH, c = i % DH;
        size_t off = (size_t)(base + r)*2304 + h*DH + c;
        sQ[r*QKV_STRIDE + c] = qkv[off];
        sK[r*QKV_STRIDE + c] = qkv[off + 768];
        sV[r*QKV_STRIDE + c] = qkv[off + 1536];
    }
    __syncthreads();

    for (int e = threadIdx.x; e < 64*64; e += 512) {
        int i = e >> 6, j = e & 63;
        const float* q = sQ + i*QKV_STRIDE;
        const float* k = sK + j*QKV_STRIDE;
        float s = 0.f;
        #pragma unroll 8
        for (int d = 0; d < DH; d++) s = fmaf(q[d], k[d], s);
        sS[i*SC_STRIDE + j] = s * scale;
    }
    __syncthreads();

    if (threadIdx.x < 64) {
        float* row = sS + threadIdx.x * SC_STRIDE;
        float mx = row[0];
        #pragma unroll 8
        for (int j = 1; j < 64; j++) mx = fmaxf(mx, row[j]);
        float sum = 0.f;
        #pragma unroll 8
        for (int j = 0; j < 64; j++) { float e = __expf(row[j] - mx); row[j] = e; sum += e; }
        float inv = 1.f / sum;
        #pragma unroll 8
        for (int j = 0; j < 64; j++) row[j] *= inv;
    }
    __syncthreads();

    for (int e = threadIdx.x; e < 64*DH; e += 512) {
        int i = e / DH, d = e % DH;
        const float* p = sS + i*SC_STRIDE;
        float s = 0.f;
        #pragma unroll 8
        for (int j = 0; j < 64; j++) s = fmaf(p[j], sV[j*QKV_STRIDE + d], s);
        out[(size_t)(base + i)*EMB + h*DH + d] = s;
    }
}

// ---------------------------------------------------------------------------
// 2x2 maxpool (32,64,128,128) -> (32,64,64,64)
// ---------------------------------------------------------------------------
__global__ void maxpool_kernel(const float* __restrict__ in, float* __restrict__ out)
{
    int idx = blockIdx.x * blockDim.x + threadIdx.x;
    if (idx >= ROWS * HW2) return;
    int ox = idx & 63;
    int oy = (idx >> 6) & 63;
    int cb = idx >> 12;
    const float* p = in + ((size_t)cb*128 + oy*2)*128 + ox*2;
    out[idx] = fmaxf(fmaxf(p[0], p[1]), fmaxf(p[128], p[129]));
}

// ---------------------------------------------------------------------------
// fc2: (2048,2048) @ (4,2048)^T + bias -> (2048,4). One warp per row.
// ---------------------------------------------------------------------------
__global__ void fc2_kernel(const float* __restrict__ h1, const float* __restrict__ w,
                           const float* __restrict__ bias, float* __restrict__ tp)
{
    int warp = (blockIdx.x * blockDim.x + threadIdx.x) >> 5;
    int lane = threadIdx.x & 31;
    if (warp >= ROWS) return;
    const float* row = h1 + (size_t)warp * HC2;
    float a0 = 0.f, a1 = 0.f, a2 = 0.f, a3 = 0.f;
    for (int k = lane; k < HC2; k += 32) {
        float hv = row[k];
        a0 = fmaf(hv, w[k],          a0);
        a1 = fmaf(hv, w[HC2   + k],  a1);
        a2 = fmaf(hv, w[2*HC2 + k],  a2);
        a3 = fmaf(hv, w[3*HC2 + k],  a3);
    }
    #pragma unroll
    for (int o = 16; o > 0; o >>= 1) {
        a0 += __shfl_xor_sync(0xffffffffu, a0, o);
        a1 += __shfl_xor_sync(0xffffffffu, a1, o);
        a2 += __shfl_xor_sync(0xffffffffu, a2, o);
        a3 += __shfl_xor_sync(0xffffffffu, a3, o);
    }
    if (lane == 0) {
        tp[warp*4 + 0] = a0 + bias[0];
        tp[warp*4 + 1] = a1 + bias[1];
        tp[warp*4 + 2] = a2 + bias[2];
        tp[warp*4 + 3] = a3 + bias[3];
    }
}

// ---------------------------------------------------------------------------
// Affine params + translate output
// ---------------------------------------------------------------------------
__global__ void params_kernel(const float* __restrict__ tp, float* __restrict__ par,
                              float* __restrict__ out_translate)
{
    int i = blockIdx.x * blockDim.x + threadIdx.x;
    if (i >= ROWS) return;
    float t0 = tp[i*4+0], t1 = tp[i*4+1], t2 = tp[i*4+2], t3 = tp[i*4+3];
    float trx = tanhf(t0);
    float trY = tanhf(t1);
    float s   = 0.3f / (1.f + expf(-t2));
    float rot = tanhf(t3) * 3.14159265358979323846f;
    float sn, cs;
    sincosf(rot, &sn, &cs);
    float x_ext = fminf(s*fabsf(cs) + s*fabsf(sn), 1.f);
    float y_ext = fminf(s*fabsf(sn) + s*fabsf(cs), 1.f);
    float txv = trx * (1.f - x_ext);
    float tyv = trY * (1.f - y_ext);
    par[i*6+0] =  s*cs;
    par[i*6+1] = -s*sn;
    par[i*6+2] =  s*sn;
    par[i*6+3] =  s*cs;
    par[i*6+4] =  txv;
    par[i*6+5] =  tyv;
    out_translate[i*2+0] = txv;
    out_translate[i*2+1] = tyv;
}

// ---------------------------------------------------------------------------
// Bilinear grid sample -> patches (B*NP, C, P, P)
// ---------------------------------------------------------------------------
__global__ void gridsample_kernel(const float* __restrict__ x,
                                  const float* __restrict__ par,
                                  float* __restrict__ out)
{
    int idx = blockIdx.x * blockDim.x + threadIdx.x;
    const int total = ROWS * CIN * PSZ * PSZ;
    if (idx >= total) return;
    int px = idx & 15;
    int py = (idx >> 4) & 15;
    int c  = (idx >> 8) % 3;
    int bp = idx / (3*256);
    int b  = bp >> 6;

    float ta = par[bp*6+0], tb = par[bp*6+1], tc = par[bp*6+2];
    float td = par[bp*6+3], txp = par[bp*6+4], typ = par[bp*6+5];

    float bxv = (2.f*px + 1.f) / 16.f - 1.f;
    float byv = (2.f*py + 1.f) / 16.f - 1.f;
    float gx = ta*bxv + tb*byv + txp;
    float gy = tc*bxv + td*byv + typ;

    float xs = ((gx + 1.f) * (float)WIMG - 1.f) * 0.5f;
    float ys = ((gy + 1.f) * (float)HIMG - 1.f) * 0.5f;
    float x0f = floorf(xs), y0f = floorf(ys);
    float wx = xs - x0f, wy = ys - y0f;
    int x0 = (int)x0f, y0 = (int)y0f;

    const float* img = x + ((size_t)b*3 + c) * (HIMG*WIMG);
    float v00 = 0.f, v01 = 0.f, v10 = 0.f, v11 = 0.f;
    bool xv0 = (x0   >= 0) & (x0   < WIMG);
    bool xv1 = (x0+1 >= 0) & (x0+1 < WIMG);
    bool yv0 = (y0   >= 0) & (y0   < HIMG);
    bool yv1 = (y0+1 >= 0) & (y0+1 < HIMG);
    if (yv0 & xv0) v00 = img[y0*WIMG + x0];
    if (yv0 & xv1) v01 = img[y0*WIMG + x0 + 1];
    if (yv1 & xv0) v10 = img[(y0+1)*WIMG + x0];
    if (yv1 & xv1) v11 = img[(y0+1)*WIMG + x0 + 1];

    out[idx] = v00*(1.f-wx)*(1.f-wy) + v01*wx*(1.f-wy)
             + v10*(1.f-wx)*wy       + v11*wx*wy;
}

// ---------------------------------------------------------------------------
// kernel_launch
// ---------------------------------------------------------------------------
extern "C" void kernel_launch(void* const* d_in, const int* in_sizes, int n_in,
                              void* d_out, int out_size)
{
    const float* x        = (const float*)d_in[0];
    const float* conv1_w  = (const float*)d_in[1];
    const float* conv1_b  = (const float*)d_in[2];
    const float* a1_in_w  = (const float*)d_in[3];
    const float* a1_in_b  = (const float*)d_in[4];
    const float* a1_qkv_w = (const float*)d_in[5];
    const float* a1_qkv_b = (const float*)d_in[6];
    const float* a1_out_w = (const float*)d_in[7];
    const float* a1_out_b = (const float*)d_in[8];
    const float* a1_proj_w= (const float*)d_in[9];
    const float* a1_proj_b= (const float*)d_in[10];
    const float* conv2_w  = (const float*)d_in[11];
    const float* conv2_b  = (const float*)d_in[12];
    const float* a2_in_w  = (const float*)d_in[13];
    const float* a2_in_b  = (const float*)d_in[14];
    const float* a2_qkv_w = (const float*)d_in[15];
    const float* a2_qkv_b = (const float*)d_in[16];
    const float* a2_out_w = (const float*)d_in[17];
    const float* a2_out_b = (const float*)d_in[18];
    const float* a2_proj_w= (const float*)d_in[19];
    const float* a2_proj_b= (const float*)d_in[20];
    const float* fc1_w    = (const float*)d_in[21];
    const float* fc1_b    = (const float*)d_in[22];
    const float* fc2_w    = (const float*)d_in[23];
    const float* fc2_b    = (const float*)d_in[24];

    float* out = (float*)d_out;
    float* out_patches   = out;
    float* out_translate = out + ROWS*CIN*PSZ*PSZ;

    float *f1, *y1, *pool, *f2, *y2, *t, *qkv, *att, *o, *h1, *tp, *par, *part;
    cudaGetSymbolAddress((void**)&f1,   g_f1);
    cudaGetSymbolAddress((void**)&y1,   g_y1);
    cudaGetSymbolAddress((void**)&pool, g_pool);
    cudaGetSymbolAddress((void**)&f2,   g_f2);
    cudaGetSymbolAddress((void**)&y2,   g_y2);
    cudaGetSymbolAddress((void**)&t,    g_t);
    cudaGetSymbolAddress((void**)&qkv,  g_qkv);
    cudaGetSymbolAddress((void**)&att,  g_att);
    cudaGetSymbolAddress((void**)&o,    g_o);
    cudaGetSymbolAddress((void**)&h1,   g_h1);
    cudaGetSymbolAddress((void**)&tp,   g_tp);
    cudaGetSymbolAddress((void**)&par,  g_par);
    cudaGetSymbolAddress((void**)&part, g_part);

    cudaFuncSetAttribute(attn_kernel,
                         cudaFuncAttributeMaxDynamicSharedMemorySize, ATTN_SMEM);

    const int MN768 = ROWS * EMB;

    // --- conv1 + relu (32,3,128,128) -> (32,64,128,128)
    conv3x3_relu2_kernel<3, 3, 128, 128>
        <<<dim3((128/16)*(128/64), BATCH*8), 256>>>(x, conv1_w, conv1_b, f1);

    // --- attention block 1
    // a1_in: 2048x768, K=16384  (split-K=2, BN=64 -> 384 blocks)
    sgemm2_kernel<64, 4><<<dim3(12, 16, 2), 256>>>(f1, a1_in_w, nullptr, nullptr,
                                                   ROWS, EMB, HW1, 0, 2, part);
    splitk_reduce_kernel<<<(MN768 + 255)/256, 256>>>(part, a1_in_b, t, MN768, EMB);
    // qkv: 2048x2304, K=768
    sgemm2_kernel<128, 8><<<dim3(18, 16, 1), 256>>>(t, a1_qkv_w, a1_qkv_b, qkv,
                                                    ROWS, 3*EMB, EMB, 0, 1, nullptr);
    attn_kernel<<<BATCH*4, 512, ATTN_SMEM>>>(qkv, att);
    // out: 2048x768, K=768 (split-K=2, BN=64)
    sgemm2_kernel<64, 4><<<dim3(12, 16, 2), 256>>>(att, a1_out_w, nullptr, nullptr,
                                                   ROWS, EMB, EMB, 0, 2, part);
    splitk_reduce_kernel<<<(MN768 + 255)/256, 256>>>(part, a1_out_b, o, MN768, EMB);
    // proj: 2048x16384, K=768
    sgemm2_kernel<128, 8><<<dim3(128, 16, 1), 256>>>(o, a1_proj_w, a1_proj_b, y1,
                                                     ROWS, HW1, EMB, 0, 1, nullptr);

    // --- maxpool
    maxpool_kernel<<<(ROWS*HW2 + 255)/256, 256>>>(y1, pool);

    // --- conv2 + relu (32,64,64,64) -> (32,64,64,64)
    conv3x3_relu2_kernel<64, 8, 64, 64>
        <<<dim3((64/16)*(64/64), BATCH*8), 256>>>(pool, conv2_w, conv2_b, f2);

    // --- attention block 2
    sgemm2_kernel<64, 4><<<dim3(12, 16, 2), 256>>>(f2, a2_in_w, nullptr, nullptr,
                                                   ROWS, EMB, HW2, 0, 2, part);
    splitk_reduce_kernel<<<(MN768 + 255)/256, 256>>>(part, a2_in_b, t, MN768, EMB);
    sgemm2_kernel<128, 8><<<dim3(18, 16, 1), 256>>>(t, a2_qkv_w, a2_qkv_b, qkv,
                                                    ROWS, 3*EMB, EMB, 0, 1, nullptr);
    attn_kernel<<<BATCH*4, 512, ATTN_SMEM>>>(qkv, att);
    sgemm2_kernel<64, 4><<<dim3(12, 16, 2), 256>>>(att, a2_out_w, nullptr, nullptr,
                                                   ROWS, EMB, EMB, 0, 2, part);
    splitk_reduce_kernel<<<(MN768 + 255)/256, 256>>>(part, a2_out_b, o, MN768, EMB);
    // proj2: 2048x4096, K=768 (BN=64 -> 1024 blocks, ~99% util)
    sgemm2_kernel<64, 4><<<dim3(64, 16, 1), 256>>>(o, a2_proj_w, a2_proj_b, y2,
                                                   ROWS, HW2, EMB, 0, 1, nullptr);

    // --- head
    sgemm2_kernel<128, 8><<<dim3(16, 16, 1), 256>>>(y2, fc1_w, fc1_b, h1,
                                                    ROWS, HC2, HW2, 1, 1, nullptr);
    fc2_kernel<<<(ROWS*32 + 255)/256, 256>>>(h1, fc2_w, fc2_b, tp);
    params_kernel<<<(ROWS + 255)/256, 256>>>(tp, par, out_translate);
    gridsample_kernel<<<(ROWS*CIN*PSZ*PSZ + 255)/256, 256>>>(x, par, out_patches);
}

// round 5
// speedup vs baseline: 1.3663x; 1.1149x over previous
#include <cuda_runtime.h>
#include <cuda_bf16.h>
#include <math.h>

// ---------------------------------------------------------------------------
// Problem constants
// ---------------------------------------------------------------------------
#define BATCH 32
#define CIN   3
#define HIMG  128
#define WIMG  128
#define PSZ   16
#define EMB   768
#define DH    192
#define ROWS  2048         // BATCH * 64
#define HW1   16384
#define HW2   4096
#define HC2   2048

typedef unsigned long long u64;

// ---------------------------------------------------------------------------
// f32x2 helpers (FFMA2 path — exact fp32, 2x FMA throughput on sm_103a)
// ---------------------------------------------------------------------------
__device__ __forceinline__ u64 pk2(float lo, float hi) {
    u64 r; asm("mov.b64 %0, {%1,%2};" : "=l"(r) : "f"(lo), "f"(hi)); return r;
}
__device__ __forceinline__ void fma2(u64& d, u64 a, u64 b) {
    asm("fma.rn.f32x2 %0, %1, %2, %0;" : "+l"(d) : "l"(a), "l"(b));
}
__device__ __forceinline__ float2 upk2(u64 v) {
    float2 f; asm("mov.b64 {%0,%1}, %2;" : "=f"(f.x), "=f"(f.y) : "l"(v)); return f;
}

// ---------------------------------------------------------------------------
// Scratch (device globals; no runtime allocation allowed)
// ---------------------------------------------------------------------------
__device__ float g_f1  [ROWS * HW1];
__device__ float g_y1  [ROWS * HW1];
__device__ float g_pool[ROWS * HW2];
__device__ float g_f2  [ROWS * HW2];
__device__ float g_y2  [ROWS * HW2];
__device__ float g_t   [ROWS * EMB];
__device__ float g_qkv [ROWS * 3 * EMB];
__device__ float g_att [ROWS * EMB];
__device__ float g_o   [ROWS * EMB];
__device__ float g_h1  [ROWS * HC2];
__device__ float g_tp  [ROWS * 4];
__device__ float g_par [ROWS * 6];
__device__ float g_part[3 * ROWS * EMB];   // split-K partials (split<=3, N<=768)

// ---------------------------------------------------------------------------
// SGEMM v3: C[M,N] = A[M,K] @ B[N,K]^T (+bias,+relu), FFMA2 inner loop,
// double-buffered smem, bank-conflict-free B layout (8 floats + 2 pad chunks),
// optional uneven split-K (partials, bias added in reduce).
// BM=128, BN=128, 256 threads, TM=8, TN=8.
// Requires M%128==0, N%128==0, K%16==0.
// ---------------------------------------------------------------------------
#define BSROW 160   // 16 chunks * 10 floats (8 data + 2 pad) for BN=128

__global__ void __launch_bounds__(256)
sgemm3_kernel(const float* __restrict__ A, const float* __restrict__ B,
              const float* __restrict__ bias, float* __restrict__ C,
              int M, int N, int K, int doRelu, int kSplit,
              float* __restrict__ part)
{
    __shared__ float As[2][16][128];
    __shared__ float Bs[2][16][BSROW];

    const int tid = threadIdx.x;
    const int tx  = tid & 15;
    const int ty  = tid >> 4;
    const int bm  = blockIdx.y * 128;
    const int bn  = blockIdx.x * 128;

    // split-K tile range (uneven allowed)
    const int tiles = K >> 4;
    int nT, kBase;
    if (kSplit > 1) {
        int tpz = tiles / kSplit;
        int rem = tiles - tpz * kSplit;
        int z = blockIdx.z;
        int st = z * tpz + (z < rem ? z : rem);
        nT = tpz + (z < rem ? 1 : 0);
        kBase = st << 4;
    } else { nT = tiles; kBase = 0; }

    // A tile load mapping: 128 rows x 16 k, 8 floats / thread
    const int alr = tid >> 1;
    const int alk = (tid & 1) * 8;
    const float* Ap = A + (size_t)(bm + alr) * K + kBase + alk;
    // B tile load mapping: 128 n-rows x 16 k, 8 floats / thread
    const int blr = tid >> 1;             // n index within tile
    const int blk = (tid & 1) * 8;        // k base
    const int boff = (blr >> 3) * 10 + (blr & 7);   // padded-chunk column
    const float* Bp = B + (size_t)(bn + blr) * K + kBase + blk;

    float4 ra0, ra1, rb0, rb1;

    // prologue: tile 0 -> buf 0
    ra0 = *(const float4*)Ap; ra1 = *(const float4*)(Ap + 4);
    rb0 = *(const float4*)Bp; rb1 = *(const float4*)(Bp + 4);
    Ap += 16; Bp += 16;
    As[0][alk+0][alr]=ra0.x; As[0][alk+1][alr]=ra0.y;
    As[0][alk+2][alr]=ra0.z; As[0][alk+3][alr]=ra0.w;
    As[0][alk+4][alr]=ra1.x; As[0][alk+5][alr]=ra1.y;
    As[0][alk+6][alr]=ra1.z; As[0][alk+7][alr]=ra1.w;
    Bs[0][blk+0][boff]=rb0.x; Bs[0][blk+1][boff]=rb0.y;
    Bs[0][blk+2][boff]=rb0.z; Bs[0][blk+3][boff]=rb0.w;
    Bs[0][blk+4][boff]=rb1.x; Bs[0][blk+5][boff]=rb1.y;
    Bs[0][blk+6][boff]=rb1.z; Bs[0][blk+7][boff]=rb1.w;
    __syncthreads();

    u64 acc[8][4];
    #pragma unroll
    for (int i = 0; i < 8; i++)
        #pragma unroll
        for (int j = 0; j < 4; j++) acc[i][j] = 0ull;

    int buf = 0;
    for (int tI = 0; tI < nT; tI++) {
        const bool hasNext = (tI + 1 < nT);
        if (hasNext) {
            ra0 = *(const float4*)Ap; ra1 = *(const float4*)(Ap + 4);
            rb0 = *(const float4*)Bp; rb1 = *(const float4*)(Bp + 4);
            Ap += 16; Bp += 16;
        }
        #pragma unroll
        for (int kk = 0; kk < 16; kk++) {
            float4 a0 = *(const float4*)&As[buf][kk][ty*8];
            float4 a1 = *(const float4*)&As[buf][kk][ty*8 + 4];
            u64 b2[4];
            const u64* bp2 = (const u64*)&Bs[buf][kk][tx*10];  // conflict-free
            #pragma unroll
            for (int j = 0; j < 4; j++) b2[j] = bp2[j];
            float av[8] = {a0.x, a0.y, a0.z, a0.w, a1.x, a1.y, a1.z, a1.w};
            #pragma unroll
            for (int i = 0; i < 8; i++) {
                u64 ap = pk2(av[i], av[i]);
                #pragma unroll
                for (int j = 0; j < 4; j++) fma2(acc[i][j], ap, b2[j]);
            }
        }
        if (hasNext) {
            const int nb = buf ^ 1;
            As[nb][alk+0][alr]=ra0.x; As[nb][alk+1][alr]=ra0.y;
            As[nb][alk+2][alr]=ra0.z; As[nb][alk+3][alr]=ra0.w;
            As[nb][alk+4][alr]=ra1.x; As[nb][alk+5][alr]=ra1.y;
            As[nb][alk+6][alr]=ra1.z; As[nb][alk+7][alr]=ra1.w;
            Bs[nb][blk+0][boff]=rb0.x; Bs[nb][blk+1][boff]=rb0.y;
            Bs[nb][blk+2][boff]=rb0.z; Bs[nb][blk+3][boff]=rb0.w;
            Bs[nb][blk+4][boff]=rb1.x; Bs[nb][blk+5][boff]=rb1.y;
            Bs[nb][blk+6][boff]=rb1.z; Bs[nb][blk+7][boff]=rb1.w;
        }
        __syncthreads();
        buf ^= 1;
    }

    if (kSplit > 1) {
        float* Cp0 = part + (size_t)blockIdx.z * M * N;
        #pragma unroll
        for (int i = 0; i < 8; i++) {
            float* Cp = Cp0 + (size_t)(bm + ty*8 + i) * N + bn + tx*8;
            #pragma unroll
            for (int j = 0; j < 4; j += 2) {
                float2 v0 = upk2(acc[i][j]);
                float2 v1 = upk2(acc[i][j+1]);
                *(float4*)(Cp + j*2) = make_float4(v0.x, v0.y, v1.x, v1.y);
            }
        }
    } else {
        float bv[8];
        #pragma unroll
        for (int j = 0; j < 8; j++) bv[j] = bias[bn + tx*8 + j];
        #pragma unroll
        for (int i = 0; i < 8; i++) {
            float* Cp = C + (size_t)(bm + ty*8 + i) * N + bn + tx*8;
            #pragma unroll
            for (int j = 0; j < 4; j += 2) {
                float2 v0 = upk2(acc[i][j]);
                float2 v1 = upk2(acc[i][j+1]);
                float4 v;
                v.x = v0.x + bv[j*2+0]; v.y = v0.y + bv[j*2+1];
                v.z = v1.x + bv[j*2+2]; v.w = v1.y + bv[j*2+3];
                if (doRelu) {
                    v.x = fmaxf(v.x, 0.f); v.y = fmaxf(v.y, 0.f);
                    v.z = fmaxf(v.z, 0.f); v.w = fmaxf(v.w, 0.f);
                }
                *(float4*)(Cp + j*2) = v;
            }
        }
    }
}

// split-K reduce: C = sum_z part[z] + bias   (S <= 3)
__global__ void splitk_reduce_kernel(const float* __restrict__ part,
                                     const float* __restrict__ bias,
                                     float* __restrict__ C, int MN, int N, int S)
{
    int idx = blockIdx.x * blockDim.x + threadIdx.x;
    if (idx >= MN) return;
    float s = bias[idx % N] + part[idx];
    if (S > 1) s += part[idx + MN];
    if (S > 2) s += part[idx + 2*MN];
    C[idx] = s;
}

// ---------------------------------------------------------------------------
// 3x3 SAME conv + relu with FFMA2. Tile 16(x) x 64(y), 8 oc per block,
// each thread: 4 pixels x 8 oc (pixel pairs packed f32x2).
// ---------------------------------------------------------------------------
template<int IC, int ICC, int HH, int WW>
__global__ void __launch_bounds__(256)
conv3x3_relu2_kernel(const float* __restrict__ in, const float* __restrict__ w,
                     const float* __restrict__ bias, float* __restrict__ out)
{
    __shared__ float  sIn[ICC][66][18];
    __shared__ float2 sW2[8][ICC][9];

    const int tx = threadIdx.x & 15;
    const int ty = threadIdx.x >> 4;
    const int tilesX = WW / 16;
    const int bx = (blockIdx.x % tilesX) * 16;
    const int by = (blockIdx.x / tilesX) * 64;
    const int b   = blockIdx.y >> 3;
    const int ocg = (blockIdx.y & 7) * 8;

    u64 a01[8], a23[8];
    #pragma unroll
    for (int oc = 0; oc < 8; oc++) { a01[oc] = 0ull; a23[oc] = 0ull; }

    for (int icc = 0; icc < IC; icc += ICC) {
        for (int i = threadIdx.x; i < ICC*66*18; i += 256) {
            int col = i % 18; int t = i / 18; int row = t % 66; int ic = t / 66;
            int gx = bx + col - 1, gy = by + row - 1;
            float v = 0.f;
            if (gx >= 0 && gx < WW && gy >= 0 && gy < HH)
                v = in[(((size_t)b*IC + icc + ic)*HH + gy)*WW + gx];
            sIn[ic][row][col] = v;
        }
        for (int i = threadIdx.x; i < 8*ICC*9; i += 256) {
            int kk = i % 9; int t = i / 9; int ic = t % ICC; int oc = t / ICC;
            float wv = w[((ocg + oc)*IC + icc + ic)*9 + kk];
            sW2[oc][ic][kk] = make_float2(wv, wv);
        }
        __syncthreads();

        #pragma unroll
        for (int ic = 0; ic < ICC; ic++) {
            #pragma unroll
            for (int ky = 0; ky < 3; ky++) {
                #pragma unroll
                for (int kx = 0; kx < 3; kx++) {
                    float iv0 = sIn[ic][ty      + ky][tx + kx];
                    float iv1 = sIn[ic][ty + 16 + ky][tx + kx];
                    float iv2 = sIn[ic][ty + 32 + ky][tx + kx];
                    float iv3 = sIn[ic][ty + 48 + ky][tx + kx];
                    u64 p01 = pk2(iv0, iv1);
                    u64 p23 = pk2(iv2, iv3);
                    #pragma unroll
                    for (int oc = 0; oc < 8; oc++) {
                        u64 wv = *(const u64*)&sW2[oc][ic][ky*3 + kx];
                        fma2(a01[oc], p01, wv);
                        fma2(a23[oc], p23, wv);
                    }
                }
            }
        }
        __syncthreads();
    }

    #pragma unroll
    for (int oc = 0; oc < 8; oc++) {
        float bv = bias[ocg + oc];
        float2 v01 = upk2(a01[oc]);
        float2 v23 = upk2(a23[oc]);
        size_t base = (((size_t)b*64 + ocg + oc)*HH + by + ty)*WW + bx + tx;
        out[base            ] = fmaxf(v01.x + bv, 0.f);
        out[base + 16ull*WW ] = fmaxf(v01.y + bv, 0.f);
        out[base + 32ull*WW ] = fmaxf(v23.x + bv, 0.f);
        out[base + 48ull*WW ] = fmaxf(v23.y + bv, 0.f);
    }
}

// ---------------------------------------------------------------------------
// MHA core: one block per (b, head). 64 tokens, dh=192. 512 threads.
// ---------------------------------------------------------------------------
#define QKV_STRIDE 193
#define SC_STRIDE  65
#define ATTN_SMEM  ((3*64*QKV_STRIDE + 64*SC_STRIDE) * (int)sizeof(float))

__global__ void attn_kernel(const float* __restrict__ qkv, float* __restrict__ out)
{
    extern __shared__ float sm[];
    float* sQ = sm;
    float* sK = sQ + 64*QKV_STRIDE;
    float* sV = sK + 64*QKV_STRIDE;
    float* sS = sV + 64*QKV_STRIDE;

    const int bh = blockIdx.x;
    const int b  = bh >> 2;
    const int h  = bh & 3;
    const int base = b * 64;
    const float scale = 0.07216878364870323f; // 1/sqrt(192)

    for (int i = threadIdx.x; i < 64*DH; i += 512) {
        int r = i / DH, c = i % DH;
        size_t off = (size_t)(base + r)*2304 + h*DH + c;
        sQ[r*QKV_STRIDE + c] = qkv[off];
        sK[r*QKV_STRIDE + c] = qkv[off + 768];
        sV[r*QKV_STRIDE + c] = qkv[off + 1536];
    }
    __syncthreads();

    for (int e = threadIdx.x; e < 64*64; e += 512) {
        int i = e >> 6, j = e & 63;
        const float* q = sQ + i*QKV_STRIDE;
        const float* k = sK + j*QKV_STRIDE;
        float s = 0.f;
        #pragma unroll 8
        for (int d = 0; d < DH; d++) s = fmaf(q[d], k[d], s);
        sS[i*SC_STRIDE + j] = s * scale;
    }
    __syncthreads();

    if (threadIdx.x < 64) {
        float* row = sS + threadIdx.x * SC_STRIDE;
        float mx = row[0];
        #pragma unroll 8
        for (int j = 1; j < 64; j++) mx = fmaxf(mx, row[j]);
        float sum = 0.f;
        #pragma unroll 8
        for (int j = 0; j < 64; j++) { float e = __expf(row[j] - mx); row[j] = e; sum += e; }
        float inv = 1.f / sum;
        #pragma unroll 8
        for (int j = 0; j < 64; j++) row[j] *= inv;
    }
    __syncthreads();

    for (int e = threadIdx.x; e < 64*DH; e += 512) {
        int i = e / DH, d = e % DH;
        const float* p = sS + i*SC_STRIDE;
        float s = 0.f;
        #pragma unroll 8
        for (int j = 0; j < 64; j++) s = fmaf(p[j], sV[j*QKV_STRIDE + d], s);
        out[(size_t)(base + i)*EMB + h*DH + d] = s;
    }
}

// ---------------------------------------------------------------------------
// 2x2 maxpool (32,64,128,128) -> (32,64,64,64)
// ---------------------------------------------------------------------------
__global__ void maxpool_kernel(const float* __restrict__ in, float* __restrict__ out)
{
    int idx = blockIdx.x * blockDim.x + threadIdx.x;
    if (idx >= ROWS * HW2) return;
    int ox = idx & 63;
    int oy = (idx >> 6) & 63;
    int cb = idx >> 12;
    const float* p = in + ((size_t)cb*128 + oy*2)*128 + ox*2;
    out[idx] = fmaxf(fmaxf(p[0], p[1]), fmaxf(p[128], p[129]));
}

// ---------------------------------------------------------------------------
// fc2: (2048,2048) @ (4,2048)^T + bias -> (2048,4). One warp per row.
// ---------------------------------------------------------------------------
__global__ void fc2_kernel(const float* __restrict__ h1, const float* __restrict__ w,
                           const float* __restrict__ bias, float* __restrict__ tp)
{
    int warp = (blockIdx.x * blockDim.x + threadIdx.x) >> 5;
    int lane = threadIdx.x & 31;
    if (warp >= ROWS) return;
    const float* row = h1 + (size_t)warp * HC2;
    float a0 = 0.f, a1 = 0.f, a2 = 0.f, a3 = 0.f;
    for (int k = lane; k < HC2; k += 32) {
        float hv = row[k];
        a0 = fmaf(hv, w[k],          a0);
        a1 = fmaf(hv, w[HC2   + k],  a1);
        a2 = fmaf(hv, w[2*HC2 + k],  a2);
        a3 = fmaf(hv, w[3*HC2 + k],  a3);
    }
    #pragma unroll
    for (int o = 16; o > 0; o >>= 1) {
        a0 += __shfl_xor_sync(0xffffffffu, a0, o);
        a1 += __shfl_xor_sync(0xffffffffu, a1, o);
        a2 += __shfl_xor_sync(0xffffffffu, a2, o);
        a3 += __shfl_xor_sync(0xffffffffu, a3, o);
    }
    if (lane == 0) {
        tp[warp*4 + 0] = a0 + bias[0];
        tp[warp*4 + 1] = a1 + bias[1];
        tp[warp*4 + 2] = a2 + bias[2];
        tp[warp*4 + 3] = a3 + bias[3];
    }
}

// ---------------------------------------------------------------------------
// Affine params + translate output
// ---------------------------------------------------------------------------
__global__ void params_kernel(const float* __restrict__ tp, float* __restrict__ par,
                              float* __restrict__ out_translate)
{
    int i = blockIdx.x * blockDim.x + threadIdx.x;
    if (i >= ROWS) return;
    float t0 = tp[i*4+0], t1 = tp[i*4+1], t2 = tp[i*4+2], t3 = tp[i*4+3];
    float trx = tanhf(t0);
    float trY = tanhf(t1);
    float s   = 0.3f / (1.f + expf(-t2));
    float rot = tanhf(t3) * 3.14159265358979323846f;
    float sn, cs;
    sincosf(rot, &sn, &cs);
    float x_ext = fminf(s*fabsf(cs) + s*fabsf(sn), 1.f);
    float y_ext = fminf(s*fabsf(sn) + s*fabsf(cs), 1.f);
    float txv = trx * (1.f - x_ext);
    float tyv = trY * (1.f - y_ext);
    par[i*6+0] =  s*cs;
    par[i*6+1] = -s*sn;
    par[i*6+2] =  s*sn;
    par[i*6+3] =  s*cs;
    par[i*6+4] =  txv;
    par[i*6+5] =  tyv;
    out_translate[i*2+0] = txv;
    out_translate[i*2+1] = tyv;
}

// ---------------------------------------------------------------------------
// Bilinear grid sample -> patches (B*NP, C, P, P)
// ---------------------------------------------------------------------------
__global__ void gridsample_kernel(const float* __restrict__ x,
                                  const float* __restrict__ par,
                                  float* __restrict__ out)
{
    int idx = blockIdx.x * blockDim.x + threadIdx.x;
    const int total = ROWS * CIN * PSZ * PSZ;
    if (idx >= total) return;
    int px = idx & 15;
    int py = (idx >> 4) & 15;
    int c  = (idx >> 8) % 3;
    int bp = idx / (3*256);
    int b  = bp >> 6;

    float ta = par[bp*6+0], tb = par[bp*6+1], tc = par[bp*6+2];
    float td = par[bp*6+3], txp = par[bp*6+4], typ = par[bp*6+5];

    float bxv = (2.f*px + 1.f) / 16.f - 1.f;
    float byv = (2.f*py + 1.f) / 16.f - 1.f;
    float gx = ta*bxv + tb*byv + txp;
    float gy = tc*bxv + td*byv + typ;

    float xs = ((gx + 1.f) * (float)WIMG - 1.f) * 0.5f;
    float ys = ((gy + 1.f) * (float)HIMG - 1.f) * 0.5f;
    float x0f = floorf(xs), y0f = floorf(ys);
    float wx = xs - x0f, wy = ys - y0f;
    int x0 = (int)x0f, y0 = (int)y0f;

    const float* img = x + ((size_t)b*3 + c) * (HIMG*WIMG);
    float v00 = 0.f, v01 = 0.f, v10 = 0.f, v11 = 0.f;
    bool xv0 = (x0   >= 0) & (x0   < WIMG);
    bool xv1 = (x0+1 >= 0) & (x0+1 < WIMG);
    bool yv0 = (y0   >= 0) & (y0   < HIMG);
    bool yv1 = (y0+1 >= 0) & (y0+1 < HIMG);
    if (yv0 & xv0) v00 = img[y0*WIMG + x0];
    if (yv0 & xv1) v01 = img[y0*WIMG + x0 + 1];
    if (yv1 & xv0) v10 = img[(y0+1)*WIMG + x0];
    if (yv1 & xv1) v11 = img[(y0+1)*WIMG + x0 + 1];

    out[idx] = v00*(1.f-wx)*(1.f-wy) + v01*wx*(1.f-wy)
             + v10*(1.f-wx)*wy       + v11*wx*wy;
}

// ---------------------------------------------------------------------------
// kernel_launch
// ---------------------------------------------------------------------------
extern "C" void kernel_launch(void* const* d_in, const int* in_sizes, int n_in,
                              void* d_out, int out_size)
{
    const float* x        = (const float*)d_in[0];
    const float* conv1_w  = (const float*)d_in[1];
    const float* conv1_b  = (const float*)d_in[2];
    const float* a1_in_w  = (const float*)d_in[3];
    const float* a1_in_b  = (const float*)d_in[4];
    const float* a1_qkv_w = (const float*)d_in[5];
    const float* a1_qkv_b = (const float*)d_in[6];
    const float* a1_out_w = (const float*)d_in[7];
    const float* a1_out_b = (const float*)d_in[8];
    const float* a1_proj_w= (const float*)d_in[9];
    const float* a1_proj_b= (const float*)d_in[10];
    const float* conv2_w  = (const float*)d_in[11];
    const float* conv2_b  = (const float*)d_in[12];
    const float* a2_in_w  = (const float*)d_in[13];
    const float* a2_in_b  = (const float*)d_in[14];
    const float* a2_qkv_w = (const float*)d_in[15];
    const float* a2_qkv_b = (const float*)d_in[16];
    const float* a2_out_w = (const float*)d_in[17];
    const float* a2_out_b = (const float*)d_in[18];
    const float* a2_proj_w= (const float*)d_in[19];
    const float* a2_proj_b= (const float*)d_in[20];
    const float* fc1_w    = (const float*)d_in[21];
    const float* fc1_b    = (const float*)d_in[22];
    const float* fc2_w    = (const float*)d_in[23];
    const float* fc2_b    = (const float*)d_in[24];

    float* out = (float*)d_out;
    float* out_patches   = out;
    float* out_translate = out + ROWS*CIN*PSZ*PSZ;

    float *f1, *y1, *pool, *f2, *y2, *t, *qkv, *att, *o, *h1, *tp, *par, *part;
    cudaGetSymbolAddress((void**)&f1,   g_f1);
    cudaGetSymbolAddress((void**)&y1,   g_y1);
    cudaGetSymbolAddress((void**)&pool, g_pool);
    cudaGetSymbolAddress((void**)&f2,   g_f2);
    cudaGetSymbolAddress((void**)&y2,   g_y2);
    cudaGetSymbolAddress((void**)&t,    g_t);
    cudaGetSymbolAddress((void**)&qkv,  g_qkv);
    cudaGetSymbolAddress((void**)&att,  g_att);
    cudaGetSymbolAddress((void**)&o,    g_o);
    cudaGetSymbolAddress((void**)&h1,   g_h1);
    cudaGetSymbolAddress((void**)&tp,   g_tp);
    cudaGetSymbolAddress((void**)&par,  g_par);
    cudaGetSymbolAddress((void**)&part, g_part);

    cudaFuncSetAttribute(attn_kernel,
                         cudaFuncAttributeMaxDynamicSharedMemorySize, ATTN_SMEM);

    const int MN768 = ROWS * EMB;

    // --- conv1 + relu (32,3,128,128) -> (32,64,128,128)
    conv3x3_relu2_kernel<3, 3, 128, 128>
        <<<dim3((128/16)*(128/64), BATCH*8), 256>>>(x, conv1_w, conv1_b, f1);

    // --- attention block 1
    // a1_in: 2048x768, K=16384, split-K=3 -> 288 blocks (~1 full wave)
    sgemm3_kernel<<<dim3(6, 16, 3), 256>>>(f1, a1_in_w, nullptr, nullptr,
                                           ROWS, EMB, HW1, 0, 3, part);
    splitk_reduce_kernel<<<(MN768 + 255)/256, 256>>>(part, a1_in_b, t, MN768, EMB, 3);
    // qkv: 2048x2304, K=768 -> 288 blocks
    sgemm3_kernel<<<dim3(18, 16, 1), 256>>>(t, a1_qkv_w, a1_qkv_b, qkv,
                                            ROWS, 3*EMB, EMB, 0, 1, nullptr);
    attn_kernel<<<BATCH*4, 512, ATTN_SMEM>>>(qkv, att);
    // out: 2048x768, K=768, split-K=3
    sgemm3_kernel<<<dim3(6, 16, 3), 256>>>(att, a1_out_w, nullptr, nullptr,
                                           ROWS, EMB, EMB, 0, 3, part);
    splitk_reduce_kernel<<<(MN768 + 255)/256, 256>>>(part, a1_out_b, o, MN768, EMB, 3);
    // proj1: 2048x16384, K=768 -> 2048 blocks
    sgemm3_kernel<<<dim3(128, 16, 1), 256>>>(o, a1_proj_w, a1_proj_b, y1,
                                             ROWS, HW1, EMB, 0, 1, nullptr);

    // --- maxpool
    maxpool_kernel<<<(ROWS*HW2 + 255)/256, 256>>>(y1, pool);

    // --- conv2 + relu (32,64,64,64) -> (32,64,64,64)
    conv3x3_relu2_kernel<64, 8, 64, 64>
        <<<dim3((64/16)*(64/64), BATCH*8), 256>>>(pool, conv2_w, conv2_b, f2);

    // --- attention block 2
    sgemm3_kernel<<<dim3(6, 16, 3), 256>>>(f2, a2_in_w, nullptr, nullptr,
                                           ROWS, EMB, HW2, 0, 3, part);
    splitk_reduce_kernel<<<(MN768 + 255)/256, 256>>>(part, a2_in_b, t, MN768, EMB, 3);
    sgemm3_kernel<<<dim3(18, 16, 1), 256>>>(t, a2_qkv_w, a2_qkv_b, qkv,
                                            ROWS, 3*EMB, EMB, 0, 1, nullptr);
    attn_kernel<<<BATCH*4, 512, ATTN_SMEM>>>(qkv, att);
    sgemm3_kernel<<<dim3(6, 16, 3), 256>>>(att, a2_out_w, nullptr, nullptr,
                                           ROWS, EMB, EMB, 0, 3, part);
    splitk_reduce_kernel<<<(MN768 + 255)/256, 256>>>(part, a2_out_b, o, MN768, EMB, 3);
    // proj2: 2048x4096, K=768 -> 512 blocks
    sgemm3_kernel<<<dim3(32, 16, 1), 256>>>(o, a2_proj_w, a2_proj_b, y2,
                                            ROWS, HW2, EMB, 0, 1, nullptr);

    // --- head
    // fc1: 2048x2048, K=4096 -> 256 blocks
    sgemm3_kernel<<<dim3(16, 16, 1), 256>>>(y2, fc1_w, fc1_b, h1,
                                            ROWS, HC2, HW2, 1, 1, nullptr);
    fc2_kernel<<<(ROWS*32 + 255)/256, 256>>>(h1, fc2_w, fc2_b, tp);
    params_kernel<<<(ROWS + 255)/256, 256>>>(tp, par, out_translate);
    gridsample_kernel<<<(ROWS*CIN*PSZ*PSZ + 255)/256, 256>>>(x, par, out_patches);
}

// round 7
// speedup vs baseline: 1.3956x; 1.0214x over previous
#include <cuda_runtime.h>
#include <cuda_bf16.h>
#include <math.h>

// ---------------------------------------------------------------------------
// Problem constants
// ---------------------------------------------------------------------------
#define BATCH 32
#define CIN   3
#define HIMG  128
#define WIMG  128
#define PSZ   16
#define EMB   768
#define DH    192
#define ROWS  2048         // BATCH * 64
#define HW1   16384
#define HW2   4096
#define HC2   2048

typedef unsigned long long u64;

// ---------------------------------------------------------------------------
// f32x2 helpers (FFMA2 path — exact fp32, 2x FMA throughput on sm_103a)
// ---------------------------------------------------------------------------
__device__ __forceinline__ u64 pk2(float lo, float hi) {
    u64 r; asm("mov.b64 %0, {%1,%2};" : "=l"(r) : "f"(lo), "f"(hi)); return r;
}
__device__ __forceinline__ void fma2(u64& d, u64 a, u64 b) {
    asm("fma.rn.f32x2 %0, %1, %2, %0;" : "+l"(d) : "l"(a), "l"(b));
}
__device__ __forceinline__ float2 upk2(u64 v) {
    float2 f; asm("mov.b64 {%0,%1}, %2;" : "=f"(f.x), "=f"(f.y) : "l"(v)); return f;
}

// ---------------------------------------------------------------------------
// Scratch (device globals; no runtime allocation allowed)
// ---------------------------------------------------------------------------
__device__ float g_f1  [ROWS * HW1];
__device__ float g_y1  [ROWS * HW1];
__device__ float g_pool[ROWS * HW2];
__device__ float g_f2  [ROWS * HW2];
__device__ float g_y2  [ROWS * HW2];
__device__ float g_t   [ROWS * EMB];
__device__ float g_qkv [ROWS * 3 * EMB];
__device__ float g_att [ROWS * EMB];
__device__ float g_o   [ROWS * EMB];
__device__ float g_h1  [ROWS * HC2];
__device__ float g_tp  [ROWS * 4];
__device__ float g_par [ROWS * 6];
__device__ float g_part[3 * ROWS * EMB];   // split-K partials (split<=3, N<=768)

// ---------------------------------------------------------------------------
// SGEMM v4: C[M,N] = A[M,K] @ B[N,K]^T (+bias,+relu), FFMA2 inner loop,
// double-buffered smem, conflict-free B layout (8 data + 2 pad float chunks),
// compile-time kSplit/relu, __launch_bounds__(256,2) to hold 2 CTAs/SM.
// BM=128, BN=128, 256 threads, TM=8, TN=8.
// Requires M%128==0, N%128==0, K%16==0.
// ---------------------------------------------------------------------------
#define BSROW 160   // 16 chunks * 10 floats (8 data + 2 pad)

template<int KSPLIT, int RELU>
__global__ void __launch_bounds__(256, 2)
sgemm4_kernel(const float* __restrict__ A, const float* __restrict__ B,
              const float* __restrict__ bias, float* __restrict__ C,
              int M, int N, int K,
              float* __restrict__ part)
{
    __shared__ float As[2][16][128];
    __shared__ float Bs[2][16][BSROW];

    const int tid = threadIdx.x;
    const int tx  = tid & 15;
    const int ty  = tid >> 4;
    const int bm  = blockIdx.y * 128;
    const int bn  = blockIdx.x * 128;

    // split-K tile range (uneven allowed)
    const int tiles = K >> 4;
    int nT, kBase;
    if (KSPLIT > 1) {
        int tpz = tiles / KSPLIT;
        int rem = tiles - tpz * KSPLIT;
        int z = blockIdx.z;
        int st = z * tpz + (z < rem ? z : rem);
        nT = tpz + (z < rem ? 1 : 0);
        kBase = st << 4;
    } else { nT = tiles; kBase = 0; }

    // A tile load mapping: 128 rows x 16 k, 8 floats / thread
    const int alr = tid >> 1;
    const int alk = (tid & 1) * 8;
    const float* Ap = A + (size_t)(bm + alr) * K + kBase + alk;
    // B tile load mapping: 128 n-rows x 16 k, 8 floats / thread
    const int blr = tid >> 1;
    const int blk = (tid & 1) * 8;
    const int boff = (blr >> 3) * 10 + (blr & 7);   // padded-chunk column
    const float* Bp = B + (size_t)(bn + blr) * K + kBase + blk;

    float4 ra0, ra1, rb0, rb1;

    // prologue: tile 0 -> buf 0
    ra0 = *(const float4*)Ap; ra1 = *(const float4*)(Ap + 4);
    rb0 = *(const float4*)Bp; rb1 = *(const float4*)(Bp + 4);
    Ap += 16; Bp += 16;
    As[0][alk+0][alr]=ra0.x; As[0][alk+1][alr]=ra0.y;
    As[0][alk+2][alr]=ra0.z; As[0][alk+3][alr]=ra0.w;
    As[0][alk+4][alr]=ra1.x; As[0][alk+5][alr]=ra1.y;
    As[0][alk+6][alr]=ra1.z; As[0][alk+7][alr]=ra1.w;
    Bs[0][blk+0][boff]=rb0.x; Bs[0][blk+1][boff]=rb0.y;
    Bs[0][blk+2][boff]=rb0.z; Bs[0][blk+3][boff]=rb0.w;
    Bs[0][blk+4][boff]=rb1.x; Bs[0][blk+5][boff]=rb1.y;
    Bs[0][blk+6][boff]=rb1.z; Bs[0][blk+7][boff]=rb1.w;
    __syncthreads();

    u64 acc[8][4];
    #pragma unroll
    for (int i = 0; i < 8; i++)
        #pragma unroll
        for (int j = 0; j < 4; j++) acc[i][j] = 0ull;

    int buf = 0;
    for (int tI = 0; tI < nT; tI++) {
        const bool hasNext = (tI + 1 < nT);
        if (hasNext) {
            ra0 = *(const float4*)Ap; ra1 = *(const float4*)(Ap + 4);
            rb0 = *(const float4*)Bp; rb1 = *(const float4*)(Bp + 4);
            Ap += 16; Bp += 16;
        }
        #pragma unroll
        for (int kk = 0; kk < 16; kk++) {
            float4 a0 = *(const float4*)&As[buf][kk][ty*8];
            float4 a1 = *(const float4*)&As[buf][kk][ty*8 + 4];
            u64 b2[4];
            const u64* bp2 = (const u64*)&Bs[buf][kk][tx*10];  // conflict-free
            #pragma unroll
            for (int j = 0; j < 4; j++) b2[j] = bp2[j];
            float av[8] = {a0.x, a0.y, a0.z, a0.w, a1.x, a1.y, a1.z, a1.w};
            #pragma unroll
            for (int i = 0; i < 8; i++) {
                u64 ap = pk2(av[i], av[i]);
                #pragma unroll
                for (int j = 0; j < 4; j++) fma2(acc[i][j], ap, b2[j]);
            }
        }
        if (hasNext) {
            const int nb = buf ^ 1;
            As[nb][alk+0][alr]=ra0.x; As[nb][alk+1][alr]=ra0.y;
            As[nb][alk+2][alr]=ra0.z; As[nb][alk+3][alr]=ra0.w;
            As[nb][alk+4][alr]=ra1.x; As[nb][alk+5][alr]=ra1.y;
            As[nb][alk+6][alr]=ra1.z; As[nb][alk+7][alr]=ra1.w;
            Bs[nb][blk+0][boff]=rb0.x; Bs[nb][blk+1][boff]=rb0.y;
            Bs[nb][blk+2][boff]=rb0.z; Bs[nb][blk+3][boff]=rb0.w;
            Bs[nb][blk+4][boff]=rb1.x; Bs[nb][blk+5][boff]=rb1.y;
            Bs[nb][blk+6][boff]=rb1.z; Bs[nb][blk+7][boff]=rb1.w;
        }
        __syncthreads();
        buf ^= 1;
    }

    if (KSPLIT > 1) {
        float* Cp0 = part + (size_t)blockIdx.z * M * N;
        #pragma unroll
        for (int i = 0; i < 8; i++) {
            float* Cp = Cp0 + (size_t)(bm + ty*8 + i) * N + bn + tx*8;
            #pragma unroll
            for (int j = 0; j < 4; j += 2) {
                float2 v0 = upk2(acc[i][j]);
                float2 v1 = upk2(acc[i][j+1]);
                *(float4*)(Cp + j*2) = make_float4(v0.x, v0.y, v1.x, v1.y);
            }
        }
    } else {
        float bv[8];
        #pragma unroll
        for (int j = 0; j < 8; j++) bv[j] = bias[bn + tx*8 + j];
        #pragma unroll
        for (int i = 0; i < 8; i++) {
            float* Cp = C + (size_t)(bm + ty*8 + i) * N + bn + tx*8;
            #pragma unroll
            for (int j = 0; j < 4; j += 2) {
                float2 v0 = upk2(acc[i][j]);
                float2 v1 = upk2(acc[i][j+1]);
                float4 v;
                v.x = v0.x + bv[j*2+0]; v.y = v0.y + bv[j*2+1];
                v.z = v1.x + bv[j*2+2]; v.w = v1.y + bv[j*2+3];
                if (RELU) {
                    v.x = fmaxf(v.x, 0.f); v.y = fmaxf(v.y, 0.f);
                    v.z = fmaxf(v.z, 0.f); v.w = fmaxf(v.w, 0.f);
                }
                *(float4*)(Cp + j*2) = v;
            }
        }
    }
}

// split-K reduce: C = sum_z part[z] + bias   (S <= 3)
__global__ void splitk_reduce_kernel(const float* __restrict__ part,
                                     const float* __restrict__ bias,
                                     float* __restrict__ C, int MN, int N, int S)
{
    int idx = blockIdx.x * blockDim.x + threadIdx.x;
    if (idx >= MN) return;
    float s = bias[idx % N] + part[idx];
    if (S > 1) s += part[idx + MN];
    if (S > 2) s += part[idx + 2*MN];
    C[idx] = s;
}

// ---------------------------------------------------------------------------
// 3x3 SAME conv + relu with FFMA2. Tile 16(x) x 64(y), 8 oc per block,
// each thread: 4 pixels x 8 oc (pixel pairs packed f32x2).
// ---------------------------------------------------------------------------
template<int IC, int ICC, int HH, int WW>
__global__ void __launch_bounds__(256)
conv3x3_relu2_kernel(const float* __restrict__ in, const float* __restrict__ w,
                     const float* __restrict__ bias, float* __restrict__ out)
{
    __shared__ float  sIn[ICC][66][18];
    __shared__ float2 sW2[8][ICC][9];

    const int tx = threadIdx.x & 15;
    const int ty = threadIdx.x >> 4;
    const int tilesX = WW / 16;
    const int bx = (blockIdx.x % tilesX) * 16;
    const int by = (blockIdx.x / tilesX) * 64;
    const int b   = blockIdx.y >> 3;
    const int ocg = (blockIdx.y & 7) * 8;

    u64 a01[8], a23[8];
    #pragma unroll
    for (int oc = 0; oc < 8; oc++) { a01[oc] = 0ull; a23[oc] = 0ull; }

    for (int icc = 0; icc < IC; icc += ICC) {
        for (int i = threadIdx.x; i < ICC*66*18; i += 256) {
            int col = i % 18; int t = i / 18; int row = t % 66; int ic = t / 66;
            int gx = bx + col - 1, gy = by + row - 1;
            float v = 0.f;
            if (gx >= 0 && gx < WW && gy >= 0 && gy < HH)
                v = in[(((size_t)b*IC + icc + ic)*HH + gy)*WW + gx];
            sIn[ic][row][col] = v;
        }
        for (int i = threadIdx.x; i < 8*ICC*9; i += 256) {
            int kk = i % 9; int t = i / 9; int ic = t % ICC; int oc = t / ICC;
            float wv = w[((ocg + oc)*IC + icc + ic)*9 + kk];
            sW2[oc][ic][kk] = make_float2(wv, wv);
        }
        __syncthreads();

        #pragma unroll
        for (int ic = 0; ic < ICC; ic++) {
            #pragma unroll
            for (int ky = 0; ky < 3; ky++) {
                #pragma unroll
                for (int kx = 0; kx < 3; kx++) {
                    float iv0 = sIn[ic][ty      + ky][tx + kx];
                    float iv1 = sIn[ic][ty + 16 + ky][tx + kx];
                    float iv2 = sIn[ic][ty + 32 + ky][tx + kx];
                    float iv3 = sIn[ic][ty + 48 + ky][tx + kx];
                    u64 p01 = pk2(iv0, iv1);
                    u64 p23 = pk2(iv2, iv3);
                    #pragma unroll
                    for (int oc = 0; oc < 8; oc++) {
                        u64 wv = *(const u64*)&sW2[oc][ic][ky*3 + kx];
                        fma2(a01[oc], p01, wv);
                        fma2(a23[oc], p23, wv);
                    }
                }
            }
        }
        __syncthreads();
    }

    #pragma unroll
    for (int oc = 0; oc < 8; oc++) {
        float bv = bias[ocg + oc];
        float2 v01 = upk2(a01[oc]);
        float2 v23 = upk2(a23[oc]);
        size_t base = (((size_t)b*64 + ocg + oc)*HH + by + ty)*WW + bx + tx;
        out[base            ] = fmaxf(v01.x + bv, 0.f);
        out[base + 16ull*WW ] = fmaxf(v01.y + bv, 0.f);
        out[base + 32ull*WW ] = fmaxf(v23.x + bv, 0.f);
        out[base + 48ull*WW ] = fmaxf(v23.y + bv, 0.f);
    }
}

// ---------------------------------------------------------------------------
// MHA core: one block per (b, head). 64 tokens, dh=192. 512 threads.
// ---------------------------------------------------------------------------
#define QKV_STRIDE 193
#define SC_STRIDE  65
#define ATTN_SMEM  ((3*64*QKV_STRIDE + 64*SC_STRIDE) * (int)sizeof(float))

__global__ void attn_kernel(const float* __restrict__ qkv, float* __restrict__ out)
{
    extern __shared__ float sm[];
    float* sQ = sm;
    float* sK = sQ + 64*QKV_STRIDE;
    float* sV = sK + 64*QKV_STRIDE;
    float* sS = sV + 64*QKV_STRIDE;

    const int bh = blockIdx.x;
    const int b  = bh >> 2;
    const int h  = bh & 3;
    const int base = b * 64;
    const float scale = 0.07216878364870323f; // 1/sqrt(192)

    for (int i = threadIdx.x; i < 64*DH; i += 512) {
        int r = i / DH, c = i % DH;
        size_t off = (size_t)(base + r)*2304 + h*DH + c;
        sQ[r*QKV_STRIDE + c] = qkv[off];
        sK[r*QKV_STRIDE + c] = qkv[off + 768];
        sV[r*QKV_STRIDE + c] = qkv[off + 1536];
    }
    __syncthreads();

    for (int e = threadIdx.x; e < 64*64; e += 512) {
        int i = e >> 6, j = e & 63;
        const float* q = sQ + i*QKV_STRIDE;
        const float* k = sK + j*QKV_STRIDE;
        float s = 0.f;
        #pragma unroll 8
        for (int d = 0; d < DH; d++) s = fmaf(q[d], k[d], s);
        sS[i*SC_STRIDE + j] = s * scale;
    }
    __syncthreads();

    if (threadIdx.x < 64) {
        float* row = sS + threadIdx.x * SC_STRIDE;
        float mx = row[0];
        #pragma unroll 8
        for (int j = 1; j < 64; j++) mx = fmaxf(mx, row[j]);
        float sum = 0.f;
        #pragma unroll 8
        for (int j = 0; j < 64; j++) { float e = __expf(row[j] - mx); row[j] = e; sum += e; }
        float inv = 1.f / sum;
        #pragma unroll 8
        for (int j = 0; j < 64; j++) row[j] *= inv;
    }
    __syncthreads();

    for (int e = threadIdx.x; e < 64*DH; e += 512) {
        int i = e / DH, d = e % DH;
        const float* p = sS + i*SC_STRIDE;
        float s = 0.f;
        #pragma unroll 8
        for (int j = 0; j < 64; j++) s = fmaf(p[j], sV[j*QKV_STRIDE + d], s);
        out[(size_t)(base + i)*EMB + h*DH + d] = s;
    }
}

// ---------------------------------------------------------------------------
// 2x2 maxpool (32,64,128,128) -> (32,64,64,64)
// ---------------------------------------------------------------------------
__global__ void maxpool_kernel(const float* __restrict__ in, float* __restrict__ out)
{
    int idx = blockIdx.x * blockDim.x + threadIdx.x;
    if (idx >= ROWS * HW2) return;
    int ox = idx & 63;
    int oy = (idx >> 6) & 63;
    int cb = idx >> 12;
    const float* p = in + ((size_t)cb*128 + oy*2)*128 + ox*2;
    out[idx] = fmaxf(fmaxf(p[0], p[1]), fmaxf(p[128], p[129]));
}

// ---------------------------------------------------------------------------
// fc2: (2048,2048) @ (4,2048)^T + bias -> (2048,4). One warp per row.
// ---------------------------------------------------------------------------
__global__ void fc2_kernel(const float* __restrict__ h1, const float* __restrict__ w,
                           const float* __restrict__ bias, float* __restrict__ tp)
{
    int warp = (blockIdx.x * blockDim.x + threadIdx.x) >> 5;
    int lane = threadIdx.x & 31;
    if (warp >= ROWS) return;
    const float* row = h1 + (size_t)warp * HC2;
    float a0 = 0.f, a1 = 0.f, a2 = 0.f, a3 = 0.f;
    for (int k = lane; k < HC2; k += 32) {
        float hv = row[k];
        a0 = fmaf(hv, w[k],          a0);
        a1 = fmaf(hv, w[HC2   + k],  a1);
        a2 = fmaf(hv, w[2*HC2 + k],  a2);
        a3 = fmaf(hv, w[3*HC2 + k],  a3);
    }
    #pragma unroll
    for (int o = 16; o > 0; o >>= 1) {
        a0 += __shfl_xor_sync(0xffffffffu, a0, o);
        a1 += __shfl_xor_sync(0xffffffffu, a1, o);
        a2 += __shfl_xor_sync(0xffffffffu, a2, o);
        a3 += __shfl_xor_sync(0xffffffffu, a3, o);
    }
    if (lane == 0) {
        tp[warp*4 + 0] = a0 + bias[0];
        tp[warp*4 + 1] = a1 + bias[1];
        tp[warp*4 + 2] = a2 + bias[2];
        tp[warp*4 + 3] = a3 + bias[3];
    }
}

// ---------------------------------------------------------------------------
// Affine params + translate output
// ---------------------------------------------------------------------------
__global__ void params_kernel(const float* __restrict__ tp, float* __restrict__ par,
                              float* __restrict__ out_translate)
{
    int i = blockIdx.x * blockDim.x + threadIdx.x;
    if (i >= ROWS) return;
    float t0 = tp[i*4+0], t1 = tp[i*4+1], t2 = tp[i*4+2], t3 = tp[i*4+3];
    float trx = tanhf(t0);
    float trY = tanhf(t1);
    float s   = 0.3f / (1.f + expf(-t2));
    float rot = tanhf(t3) * 3.14159265358979323846f;
    float sn, cs;
    sincosf(rot, &sn, &cs);
    float x_ext = fminf(s*fabsf(cs) + s*fabsf(sn), 1.f);
    float y_ext = fminf(s*fabsf(sn) + s*fabsf(cs), 1.f);
    float txv = trx * (1.f - x_ext);
    float tyv = trY * (1.f - y_ext);
    par[i*6+0] =  s*cs;
    par[i*6+1] = -s*sn;
    par[i*6+2] =  s*sn;
    par[i*6+3] =  s*cs;
    par[i*6+4] =  txv;
    par[i*6+5] =  tyv;
    out_translate[i*2+0] = txv;
    out_translate[i*2+1] = tyv;
}

// ---------------------------------------------------------------------------
// Bilinear grid sample -> patches (B*NP, C, P, P)
// ---------------------------------------------------------------------------
__global__ void gridsample_kernel(const float* __restrict__ x,
                                  const float* __restrict__ par,
                                  float* __restrict__ out)
{
    int idx = blockIdx.x * blockDim.x + threadIdx.x;
    const int total = ROWS * CIN * PSZ * PSZ;
    if (idx >= total) return;
    int px = idx & 15;
    int py = (idx >> 4) & 15;
    int c  = (idx >> 8) % 3;
    int bp = idx / (3*256);
    int b  = bp >> 6;

    float ta = par[bp*6+0], tb = par[bp*6+1], tc = par[bp*6+2];
    float td = par[bp*6+3], txp = par[bp*6+4], typ = par[bp*6+5];

    float bxv = (2.f*px + 1.f) / 16.f - 1.f;
    float byv = (2.f*py + 1.f) / 16.f - 1.f;
    float gx = ta*bxv + tb*byv + txp;
    float gy = tc*bxv + td*byv + typ;

    float xs = ((gx + 1.f) * (float)WIMG - 1.f) * 0.5f;
    float ys = ((gy + 1.f) * (float)HIMG - 1.f) * 0.5f;
    float x0f = floorf(xs), y0f = floorf(ys);
    float wx = xs - x0f, wy = ys - y0f;
    int x0 = (int)x0f, y0 = (int)y0f;

    const float* img = x + ((size_t)b*3 + c) * (HIMG*WIMG);
    float v00 = 0.f, v01 = 0.f, v10 = 0.f, v11 = 0.f;
    bool xv0 = (x0   >= 0) & (x0   < WIMG);
    bool xv1 = (x0+1 >= 0) & (x0+1 < WIMG);
    bool yv0 = (y0   >= 0) & (y0   < HIMG);
    bool yv1 = (y0+1 >= 0) & (y0+1 < HIMG);
    if (yv0 & xv0) v00 = img[y0*WIMG + x0];
    if (yv0 & xv1) v01 = img[y0*WIMG + x0 + 1];
    if (yv1 & xv0) v10 = img[(y0+1)*WIMG + x0];
    if (yv1 & xv1) v11 = img[(y0+1)*WIMG + x0 + 1];

    out[idx] = v00*(1.f-wx)*(1.f-wy) + v01*wx*(1.f-wy)
             + v10*(1.f-wx)*wy       + v11*wx*wy;
}

// ---------------------------------------------------------------------------
// kernel_launch
// ---------------------------------------------------------------------------
extern "C" void kernel_launch(void* const* d_in, const int* in_sizes, int n_in,
                              void* d_out, int out_size)
{
    const float* x        = (const float*)d_in[0];
    const float* conv1_w  = (const float*)d_in[1];
    const float* conv1_b  = (const float*)d_in[2];
    const float* a1_in_w  = (const float*)d_in[3];
    const float* a1_in_b  = (const float*)d_in[4];
    const float* a1_qkv_w = (const float*)d_in[5];
    const float* a1_qkv_b = (const float*)d_in[6];
    const float* a1_out_w = (const float*)d_in[7];
    const float* a1_out_b = (const float*)d_in[8];
    const float* a1_proj_w= (const float*)d_in[9];
    const float* a1_proj_b= (const float*)d_in[10];
    const float* conv2_w  = (const float*)d_in[11];
    const float* conv2_b  = (const float*)d_in[12];
    const float* a2_in_w  = (const float*)d_in[13];
    const float* a2_in_b  = (const float*)d_in[14];
    const float* a2_qkv_w = (const float*)d_in[15];
    const float* a2_qkv_b = (const float*)d_in[16];
    const float* a2_out_w = (const float*)d_in[17];
    const float* a2_out_b = (const float*)d_in[18];
    const float* a2_proj_w= (const float*)d_in[19];
    const float* a2_proj_b= (const float*)d_in[20];
    const float* fc1_w    = (const float*)d_in[21];
    const float* fc1_b    = (const float*)d_in[22];
    const float* fc2_w    = (const float*)d_in[23];
    const float* fc2_b    = (const float*)d_in[24];

    float* out = (float*)d_out;
    float* out_patches   = out;
    float* out_translate = out + ROWS*CIN*PSZ*PSZ;

    float *f1, *y1, *pool, *f2, *y2, *t, *qkv, *att, *o, *h1, *tp, *par, *part;
    cudaGetSymbolAddress((void**)&f1,   g_f1);
    cudaGetSymbolAddress((void**)&y1,   g_y1);
    cudaGetSymbolAddress((void**)&pool, g_pool);
    cudaGetSymbolAddress((void**)&f2,   g_f2);
    cudaGetSymbolAddress((void**)&y2,   g_y2);
    cudaGetSymbolAddress((void**)&t,    g_t);
    cudaGetSymbolAddress((void**)&qkv,  g_qkv);
    cudaGetSymbolAddress((void**)&att,  g_att);
    cudaGetSymbolAddress((void**)&o,    g_o);
    cudaGetSymbolAddress((void**)&h1,   g_h1);
    cudaGetSymbolAddress((void**)&tp,   g_tp);
    cudaGetSymbolAddress((void**)&par,  g_par);
    cudaGetSymbolAddress((void**)&part, g_part);

    cudaFuncSetAttribute(attn_kernel,
                         cudaFuncAttributeMaxDynamicSharedMemorySize, ATTN_SMEM);

    const int MN768 = ROWS * EMB;

    // --- conv1 + relu (32,3,128,128) -> (32,64,128,128)
    conv3x3_relu2_kernel<3, 3, 128, 128>
        <<<dim3((128/16)*(128/64), BATCH*8), 256>>>(x, conv1_w, conv1_b, f1);

    // --- attention block 1
    // a1_in: 2048x768, K=16384, split-K=3 -> 288 blocks
    sgemm4_kernel<3,0><<<dim3(6, 16, 3), 256>>>(f1, a1_in_w, nullptr, nullptr,
                                                ROWS, EMB, HW1, part);
    splitk_reduce_kernel<<<(MN768 + 255)/256, 256>>>(part, a1_in_b, t, MN768, EMB, 3);
    // qkv: 2048x2304, K=768 -> 288 blocks
    sgemm4_kernel<1,0><<<dim3(18, 16, 1), 256>>>(t, a1_qkv_w, a1_qkv_b, qkv,
                                                 ROWS, 3*EMB, EMB, nullptr);
    attn_kernel<<<BATCH*4, 512, ATTN_SMEM>>>(qkv, att);
    // out: 2048x768, K=768, split-K=3
    sgemm4_kernel<3,0><<<dim3(6, 16, 3), 256>>>(att, a1_out_w, nullptr, nullptr,
                                                ROWS, EMB, EMB, part);
    splitk_reduce_kernel<<<(MN768 + 255)/256, 256>>>(part, a1_out_b, o, MN768, EMB, 3);
    // proj1: 2048x16384, K=768 -> 2048 blocks
    sgemm4_kernel<1,0><<<dim3(128, 16, 1), 256>>>(o, a1_proj_w, a1_proj_b, y1,
                                                  ROWS, HW1, EMB, nullptr);

    // --- maxpool
    maxpool_kernel<<<(ROWS*HW2 + 255)/256, 256>>>(y1, pool);

    // --- conv2 + relu (32,64,64,64) -> (32,64,64,64)
    conv3x3_relu2_kernel<64, 8, 64, 64>
        <<<dim3((64/16)*(64/64), BATCH*8), 256>>>(pool, conv2_w, conv2_b, f2);

    // --- attention block 2
    sgemm4_kernel<3,0><<<dim3(6, 16, 3), 256>>>(f2, a2_in_w, nullptr, nullptr,
                                                ROWS, EMB, HW2, part);
    splitk_reduce_kernel<<<(MN768 + 255)/256, 256>>>(part, a2_in_b, t, MN768, EMB, 3);
    sgemm4_kernel<1,0><<<dim3(18, 16, 1), 256>>>(t, a2_qkv_w, a2_qkv_b, qkv,
                                                 ROWS, 3*EMB, EMB, nullptr);
    attn_kernel<<<BATCH*4, 512, ATTN_SMEM>>>(qkv, att);
    sgemm4_kernel<3,0><<<dim3(6, 16, 3), 256>>>(att, a2_out_w, nullptr, nullptr,
                                                ROWS, EMB, EMB, part);
    splitk_reduce_kernel<<<(MN768 + 255)/256, 256>>>(part, a2_out_b, o, MN768, EMB, 3);
    // proj2: 2048x4096, K=768 -> 512 blocks
    sgemm4_kernel<1,0><<<dim3(32, 16, 1), 256>>>(o, a2_proj_w, a2_proj_b, y2,
                                                 ROWS, HW2, EMB, nullptr);

    // --- head
    // fc1: 2048x2048, K=4096 -> 256 blocks, fused relu
    sgemm4_kernel<1,1><<<dim3(16, 16, 1), 256>>>(y2, fc1_w, fc1_b, h1,
                                                 ROWS, HC2, HW2, nullptr);
    fc2_kernel<<<(ROWS*32 + 255)/256, 256>>>(h1, fc2_w, fc2_b, tp);
    params_kernel<<<(ROWS + 255)/256, 256>>>(tp, par, out_translate);
    gridsample_kernel<<<(ROWS*CIN*PSZ*PSZ + 255)/256, 256>>>(x, par, out_patches);
}